// round 6
// baseline (speedup 1.0000x reference)
#include <cuda_runtime.h>
#include <cmath>

#define Nn    768
#define CSd   384
#define NPROJ 1152
#define DOUT  2112
#define INFV  100000.0f

__device__ float g_proj [Nn * NPROJ];
__device__ float g_wcat [NPROJ * CSd];
__device__ float g_bcat [NPROJ];
__device__ float g_k    [Nn * 192];
__device__ float g_v    [Nn * 192];
__device__ float g_qpts [Nn * 144];
__device__ float g_kpts [Nn * 144];
__device__ float g_vpts [Nn * 288];
__device__ float g_logits[(size_t)12 * Nn * Nn];
__device__ float g_cat  [Nn * DOUT];

__device__ __forceinline__ void ffma2(unsigned long long& d,
                                      unsigned long long a,
                                      unsigned long long b) {
    asm("fma.rn.f32x2 %0, %1, %2, %0;" : "+l"(d) : "l"(a), "l"(b));
}
union F2U { unsigned long long u; float2 f; };

// ---------------- K0a: concat projection weights ----------------
__global__ void copy_weights(const float* __restrict__ wq,  const float* __restrict__ bq,
                             const float* __restrict__ wkv, const float* __restrict__ bkv,
                             const float* __restrict__ wqp, const float* __restrict__ bqp,
                             const float* __restrict__ wkvp,const float* __restrict__ bkvp) {
    int idx = blockIdx.x * 256 + threadIdx.x;
    if (idx < NPROJ * CSd) {
        int r = idx / CSd, k = idx - r * CSd;
        float v;
        if      (r < 192) v = wq  [ r        * CSd + k];
        else if (r < 576) v = wkv [(r - 192) * CSd + k];
        else if (r < 720) v = wqp [(r - 576) * CSd + k];
        else              v = wkvp[(r - 720) * CSd + k];
        g_wcat[idx] = v;
    }
    if (idx < NPROJ) {
        int r = idx;
        g_bcat[r] = (r < 192) ? bq[r] : (r < 576) ? bkv[r-192]
                  : (r < 720) ? bqp[r-576] : bkvp[r-720];
    }
}

// ---------------- generic TN GEMM: C = A[M,K] * B[NC,K]^T + bias ----------------
template<int MODE>
__global__ void gemm_tn(const float* __restrict__ Aext, const float* __restrict__ Bext,
                        const float* __restrict__ biasext, float* __restrict__ Cext) {
    constexpr int KK = (MODE == 0) ? CSd : DOUT;
    constexpr int NC = (MODE == 0) ? NPROJ : CSd;
    const float* A    = (MODE == 0) ? Aext   : g_cat;
    const float* B    = (MODE == 0) ? g_wcat : Bext;
    const float* bias = (MODE == 0) ? g_bcat : biasext;
    float*       C    = (MODE == 0) ? g_proj : Cext;

    __shared__ float As[64][17];
    __shared__ float Bs[64][17];
    int t  = threadIdx.x;
    int m0 = blockIdx.y * 64, n0 = blockIdx.x * 64;
    int lr = t >> 2, lc = (t & 3) * 4;
    int ty = (t >> 4) * 4, tx = (t & 15) * 4;
    float acc[4][4] = {};

    for (int k0 = 0; k0 < KK; k0 += 16) {
        __syncthreads();
        float4 a4 = *(const float4*)(A + (size_t)(m0 + lr) * KK + k0 + lc);
        float4 b4 = *(const float4*)(B + (size_t)(n0 + lr) * KK + k0 + lc);
        As[lr][lc] = a4.x; As[lr][lc+1] = a4.y; As[lr][lc+2] = a4.z; As[lr][lc+3] = a4.w;
        Bs[lr][lc] = b4.x; Bs[lr][lc+1] = b4.y; Bs[lr][lc+2] = b4.z; Bs[lr][lc+3] = b4.w;
        __syncthreads();
        #pragma unroll
        for (int kk = 0; kk < 16; kk++) {
            float av[4], bv[4];
            #pragma unroll
            for (int r = 0; r < 4; r++) av[r] = As[ty + r][kk];
            #pragma unroll
            for (int c = 0; c < 4; c++) bv[c] = Bs[tx + c][kk];
            #pragma unroll
            for (int r = 0; r < 4; r++)
                #pragma unroll
                for (int c = 0; c < 4; c++)
                    acc[r][c] = fmaf(av[r], bv[c], acc[r][c]);
        }
    }
    #pragma unroll
    for (int r = 0; r < 4; r++)
        #pragma unroll
        for (int c = 0; c < 4; c++)
            C[(size_t)(m0 + ty + r) * NC + n0 + tx + c] = acc[r][c] + bias[n0 + tx + c];
}

// ---------------- K0b: rotate points, repack k/v ----------------
__global__ void prep_pts(const float* __restrict__ rot, const float* __restrict__ trans) {
    int n = blockIdx.x;
    const float* pr = g_proj + (size_t)n * NPROJ;
    float R[9];
    #pragma unroll
    for (int e = 0; e < 9; e++) R[e] = rot[n * 9 + e];
    float tr[3] = {trans[n*3+0], trans[n*3+1], trans[n*3+2]};

    for (int t = threadIdx.x; t < 960; t += blockDim.x) {
        if (t < 384) {                       // kv repack
            int h = t >> 5, c = t & 31;
            float v = pr[192 + h * 32 + c];
            if (c < 16) g_k[n * 192 + h * 16 + c] = v;
            else        g_v[n * 192 + h * 16 + (c - 16)] = v;
        } else if (t < 528) {                // q_pts
            int e = t - 384;                 // 0..143
            int g = e / 3, ax = e - g * 3;
            const float* src = pr + 576 + g * 3;
            g_qpts[n * 144 + e] =
                R[ax*3+0]*src[0] + R[ax*3+1]*src[1] + R[ax*3+2]*src[2] + tr[ax];
        } else {                             // k_pts / v_pts
            int e2 = t - 528;                // 0..431
            int g = e2 / 3, ax = e2 - g * 3; // g = h*12 + pp
            const float* src = pr + 720 + g * 3;
            float val = R[ax*3+0]*src[0] + R[ax*3+1]*src[1] + R[ax*3+2]*src[2] + tr[ax];
            int h = g / 12, pp = g - h * 12;
            if (pp < 4) g_kpts[n * 144 + h * 12 + pp * 3 + ax] = val;
            else        g_vpts[n * 288 + h * 24 + (pp - 4) * 3 + ax] = val;
        }
    }
}

// ---------------- K1: fused logits (qk + bias + points + mask) ----------------
#define SM1_BYTES (17148 * 4)
__global__ void attn_logits(const float* __restrict__ z,   const float* __restrict__ w_b,
                            const float* __restrict__ b_b, const float* __restrict__ hwraw,
                            const float* __restrict__ mask) {
    extern __shared__ float sm[];
    float* sz    = sm;            // 32 x 132
    float* sk    = sm + 4224;     // 32 x 196
    float* skp   = sm + 10496;    // 32 x 148
    float* swb   = sm + 15232;    // 12 x 128
    float* sq    = sm + 16768;    // 192
    float* sqp   = sm + 16960;    // 144
    float* shw   = sm + 17104;    // 12
    float* smask = sm + 17116;    // 32

    const int i = blockIdx.x;
    const int tid = threadIdx.x;
    const int wid = tid >> 5, lane = tid & 31;

    if (tid < 48) ((float4*)sq )[tid] = ((const float4*)(g_proj + (size_t)i * NPROJ))[tid];
    if (tid < 36) ((float4*)sqp)[tid] = ((const float4*)(g_qpts + (size_t)i * 144))[tid];
    ((float4*)swb)[tid] = ((const float4*)w_b)[tid];   // 384 float4
    if (tid < 12) {
        float x = hwraw[tid];
        float sp = (x > 20.f) ? x : log1pf(expf(x));
        shw[tid] = sp * 0.13608276348795434f;          // * sqrt(1/54)
    }
    __syncthreads();

    float qreg[16], qp[12];
    #pragma unroll
    for (int c4 = 0; c4 < 4; c4++) {
        float4 v = *(const float4*)(sq + wid * 16 + c4 * 4);
        qreg[c4*4+0] = v.x; qreg[c4*4+1] = v.y; qreg[c4*4+2] = v.z; qreg[c4*4+3] = v.w;
    }
    #pragma unroll
    for (int c4 = 0; c4 < 3; c4++) {
        float4 v = *(const float4*)(sqp + wid * 12 + c4 * 4);
        qp[c4*4+0] = v.x; qp[c4*4+1] = v.y; qp[c4*4+2] = v.z; qp[c4*4+3] = v.w;
    }
    const float hw = shw[wid];
    const float bb = b_b[wid];
    const float mi = mask[i];
    float* lrow = g_logits + ((size_t)wid * Nn + i) * Nn;

    for (int j0 = 0; j0 < Nn; j0 += 32) {
        __syncthreads();
        for (int idx = tid; idx < 1024; idx += 384) {
            int jj = idx >> 5, c4 = idx & 31;
            float4 v = ((const float4*)z)[((size_t)i * Nn + j0 + jj) * 32 + c4];
            float* d = sz + jj * 132 + c4 * 4;
            d[0] = v.x; d[1] = v.y; d[2] = v.z; d[3] = v.w;
        }
        for (int idx = tid; idx < 1536; idx += 384) {
            int jj = idx / 48, c4 = idx - jj * 48;
            float4 v = ((const float4*)g_k)[(size_t)(j0 + jj) * 48 + c4];
            float* d = sk + jj * 196 + c4 * 4;
            d[0] = v.x; d[1] = v.y; d[2] = v.z; d[3] = v.w;
        }
        for (int idx = tid; idx < 1152; idx += 384) {
            int jj = idx / 36, c4 = idx - jj * 36;
            float4 v = ((const float4*)g_kpts)[(size_t)(j0 + jj) * 36 + c4];
            float* d = skp + jj * 148 + c4 * 4;
            d[0] = v.x; d[1] = v.y; d[2] = v.z; d[3] = v.w;
        }
        if (tid < 32) smask[tid] = mask[j0 + tid];
        __syncthreads();

        // z . w_b (packed f32x2)
        const float* zr  = sz  + lane * 132;
        const float* wbr = swb + wid * 128;
        unsigned long long p0 = 0ull, p1 = 0ull;
        #pragma unroll
        for (int c = 0; c < 128; c += 4) {
            ulonglong2 zz = *(const ulonglong2*)(zr  + c);
            ulonglong2 ww = *(const ulonglong2*)(wbr + c);
            ffma2(p0, zz.x, ww.x);
            ffma2(p1, zz.y, ww.y);
        }
        F2U u0, u1; u0.u = p0; u1.u = p1;
        float bterm = u0.f.x + u0.f.y + u1.f.x + u1.f.y + bb;

        // q . k
        const float* kr = sk + lane * 196 + wid * 16;
        float qk = 0.f;
        #pragma unroll
        for (int c4 = 0; c4 < 4; c4++) {
            float4 v = *(const float4*)(kr + c4 * 4);
            qk = fmaf(qreg[c4*4+0], v.x, qk);
            qk = fmaf(qreg[c4*4+1], v.y, qk);
            qk = fmaf(qreg[c4*4+2], v.z, qk);
            qk = fmaf(qreg[c4*4+3], v.w, qk);
        }

        // point distances
        const float* kpr = skp + lane * 148 + wid * 12;
        float d2 = 0.f;
        #pragma unroll
        for (int c4 = 0; c4 < 3; c4++) {
            float4 v = *(const float4*)(kpr + c4 * 4);
            float d0 = qp[c4*4+0] - v.x, d1 = qp[c4*4+1] - v.y;
            float d22 = qp[c4*4+2] - v.z, d3 = qp[c4*4+3] - v.w;
            d2 = fmaf(d0, d0, d2); d2 = fmaf(d1, d1, d2);
            d2 = fmaf(d22, d22, d2); d2 = fmaf(d3, d3, d2);
        }

        lrow[j0 + lane] = qk * 0.14433756729740643f
                        + 0.5773502691896258f * bterm
                        - 0.5f * hw * d2
                        + INFV * (mi * smask[lane] - 1.f);
    }
}

// ---------------- K2: softmax rows, in place ----------------
__global__ void softmax_rows() {
    const int i = blockIdx.x, h = blockIdx.y;
    float* row = g_logits + ((size_t)h * Nn + i) * Nn;
    const int t = threadIdx.x;   // 256
    float v0 = row[t], v1 = row[t + 256], v2 = row[t + 512];

    __shared__ float sred[8];
    float m = fmaxf(v0, fmaxf(v1, v2));
    #pragma unroll
    for (int off = 16; off; off >>= 1) m = fmaxf(m, __shfl_xor_sync(0xffffffffu, m, off));
    if ((t & 31) == 0) sred[t >> 5] = m;
    __syncthreads();
    float M = sred[0];
    #pragma unroll
    for (int k = 1; k < 8; k++) M = fmaxf(M, sred[k]);
    __syncthreads();

    float e0 = __expf(v0 - M), e1 = __expf(v1 - M), e2 = __expf(v2 - M);
    float s = e0 + e1 + e2;
    #pragma unroll
    for (int off = 16; off; off >>= 1) s += __shfl_xor_sync(0xffffffffu, s, off);
    if ((t & 31) == 0) sred[t >> 5] = s;
    __syncthreads();
    float S = 0.f;
    #pragma unroll
    for (int k = 0; k < 8; k++) S += sred[k];
    float inv = 1.0f / S;
    row[t] = e0 * inv; row[t + 256] = e1 * inv; row[t + 512] = e2 * inv;
}

// ---------------- K3: fused accumulation: o, o_pt(+frame), o_pair ----------------
#define SM3_BYTES (19840 * 4)
__global__ void attn_accum(const float* __restrict__ z,
                           const float* __restrict__ rot, const float* __restrict__ trans) {
    extern __shared__ float sm[];
    float* sz  = sm;            // 32 x 132
    float* sv  = sm + 4224;     // 32 x 196
    float* svp = sm + 10496;    // 32 x 292

    const int i = blockIdx.x;
    const int tid = threadIdx.x;
    const int wid = tid >> 5, lane = tid & 31;

    float acc_o[16] = {};
    float acc_opt[24] = {};
    float4 accp = {0.f, 0.f, 0.f, 0.f};
    const float* lrow = g_logits + ((size_t)wid * Nn + i) * Nn;

    for (int j0 = 0; j0 < Nn; j0 += 32) {
        __syncthreads();
        for (int idx = tid; idx < 1024; idx += 384) {
            int jj = idx >> 5, c4 = idx & 31;
            float4 v = ((const float4*)z)[((size_t)i * Nn + j0 + jj) * 32 + c4];
            float* d = sz + jj * 132 + c4 * 4;
            d[0] = v.x; d[1] = v.y; d[2] = v.z; d[3] = v.w;
        }
        for (int idx = tid; idx < 1536; idx += 384) {
            int jj = idx / 48, c4 = idx - jj * 48;
            float4 v = ((const float4*)g_v)[(size_t)(j0 + jj) * 48 + c4];
            float* d = sv + jj * 196 + c4 * 4;
            d[0] = v.x; d[1] = v.y; d[2] = v.z; d[3] = v.w;
        }
        for (int idx = tid; idx < 2304; idx += 384) {
            int jj = idx / 72, c4 = idx - jj * 72;
            float4 v = ((const float4*)g_vpts)[(size_t)(j0 + jj) * 72 + c4];
            float* d = svp + jj * 292 + c4 * 4;
            d[0] = v.x; d[1] = v.y; d[2] = v.z; d[3] = v.w;
        }
        __syncthreads();

        float w = lrow[j0 + lane];

        const float* vr = sv + lane * 196 + wid * 16;
        #pragma unroll
        for (int c4 = 0; c4 < 4; c4++) {
            float4 v = *(const float4*)(vr + c4 * 4);
            acc_o[c4*4+0] = fmaf(w, v.x, acc_o[c4*4+0]);
            acc_o[c4*4+1] = fmaf(w, v.y, acc_o[c4*4+1]);
            acc_o[c4*4+2] = fmaf(w, v.z, acc_o[c4*4+2]);
            acc_o[c4*4+3] = fmaf(w, v.w, acc_o[c4*4+3]);
        }
        const float* vpr = svp + lane * 292 + wid * 24;
        #pragma unroll
        for (int c4 = 0; c4 < 6; c4++) {
            float4 v = *(const float4*)(vpr + c4 * 4);
            acc_opt[c4*4+0] = fmaf(w, v.x, acc_opt[c4*4+0]);
            acc_opt[c4*4+1] = fmaf(w, v.y, acc_opt[c4*4+1]);
            acc_opt[c4*4+2] = fmaf(w, v.z, acc_opt[c4*4+2]);
            acc_opt[c4*4+3] = fmaf(w, v.w, acc_opt[c4*4+3]);
        }
        // o_pair: lane owns z columns [4*lane, 4*lane+4)
        #pragma unroll
        for (int jj = 0; jj < 32; jj++) {
            float wj = __shfl_sync(0xffffffffu, w, jj);
            float4 z4 = *(const float4*)(sz + jj * 132 + lane * 4);
            accp.x = fmaf(wj, z4.x, accp.x);
            accp.y = fmaf(wj, z4.y, accp.y);
            accp.z = fmaf(wj, z4.z, accp.z);
            accp.w = fmaf(wj, z4.w, accp.w);
        }
    }

    #pragma unroll
    for (int off = 16; off; off >>= 1) {
        #pragma unroll
        for (int c = 0; c < 16; c++) acc_o[c]  += __shfl_xor_sync(0xffffffffu, acc_o[c],  off);
        #pragma unroll
        for (int e = 0; e < 24; e++) acc_opt[e] += __shfl_xor_sync(0xffffffffu, acc_opt[e], off);
    }

    float* crow = g_cat + (size_t)i * DOUT;
    *(float4*)(crow + 576 + wid * 128 + lane * 4) = accp;   // o_pair

    if (lane == 0) {
        #pragma unroll
        for (int c = 0; c < 16; c++) crow[wid * 16 + c] = acc_o[c];   // o
        float R[9];
        #pragma unroll
        for (int e = 0; e < 9; e++) R[e] = rot[i * 9 + e];
        float t0 = trans[i*3+0], t1 = trans[i*3+1], t2 = trans[i*3+2];
        #pragma unroll
        for (int p = 0; p < 8; p++) {
            float dx = acc_opt[p*3+0] - t0;
            float dy = acc_opt[p*3+1] - t1;
            float dz = acc_opt[p*3+2] - t2;
            float lx = R[0]*dx + R[3]*dy + R[6]*dz;   // R^T * d
            float ly = R[1]*dx + R[4]*dy + R[7]*dz;
            float lz = R[2]*dx + R[5]*dy + R[8]*dz;
            crow[192 + (wid*8+p)*3 + 0] = lx;
            crow[192 + (wid*8+p)*3 + 1] = ly;
            crow[192 + (wid*8+p)*3 + 2] = lz;
            crow[480 + wid*8 + p] = sqrtf(lx*lx + ly*ly + lz*lz + 1e-8f);
        }
    }
}

// ---------------- host ----------------
extern "C" void kernel_launch(void* const* d_in, const int* in_sizes, int n_in,
                              void* d_out, int out_size) {
    const float* s      = (const float*)d_in[0];
    const float* z      = (const float*)d_in[1];
    const float* rot    = (const float*)d_in[2];
    const float* trans  = (const float*)d_in[3];
    const float* mask   = (const float*)d_in[4];
    const float* w_q    = (const float*)d_in[5];
    const float* b_q    = (const float*)d_in[6];
    const float* w_kv   = (const float*)d_in[7];
    const float* b_kv   = (const float*)d_in[8];
    const float* w_qp   = (const float*)d_in[9];
    const float* b_qp   = (const float*)d_in[10];
    const float* w_kvp  = (const float*)d_in[11];
    const float* b_kvp  = (const float*)d_in[12];
    const float* w_b    = (const float*)d_in[13];
    const float* b_b    = (const float*)d_in[14];
    const float* hw     = (const float*)d_in[15];
    const float* w_out  = (const float*)d_in[16];
    const float* b_out  = (const float*)d_in[17];
    float* out = (float*)d_out;

    cudaFuncSetAttribute(attn_logits, cudaFuncAttributeMaxDynamicSharedMemorySize, SM1_BYTES);
    cudaFuncSetAttribute(attn_accum,  cudaFuncAttributeMaxDynamicSharedMemorySize, SM3_BYTES);

    copy_weights<<<(NPROJ * CSd + 255) / 256, 256>>>(w_q, b_q, w_kv, b_kv,
                                                     w_qp, b_qp, w_kvp, b_kvp);
    gemm_tn<0><<<dim3(NPROJ / 64, Nn / 64), 256>>>(s, nullptr, nullptr, nullptr);
    prep_pts<<<Nn, 128>>>(rot, trans);
    attn_logits<<<Nn, 384, SM1_BYTES>>>(z, w_b, b_b, hw, mask);
    softmax_rows<<<dim3(Nn, 12), 256>>>();
    attn_accum<<<Nn, 384, SM3_BYTES>>>(z, rot, trans);
    gemm_tn<1><<<dim3(CSd / 64, Nn / 64), 256>>>(nullptr, w_out, b_out, out);
}

// round 7
// speedup vs baseline: 2.8359x; 2.8359x over previous
#include <cuda_runtime.h>
#include <cmath>

#define Nn    768
#define CSd   384
#define NPROJ 1152
#define DOUT  2112
#define INFV  100000.0f

__device__ float g_proj [Nn * NPROJ];
__device__ float g_wcat [NPROJ * CSd];
__device__ float g_bcat [NPROJ];
__device__ float g_kh  [12 * Nn * 16];
__device__ float g_vh  [12 * Nn * 16];
__device__ float g_kph [12 * Nn * 12];
__device__ float g_vph [12 * Nn * 24];
__device__ float g_qpts[Nn * 144];
__device__ float g_bias[(size_t)12 * Nn * Nn];
__device__ float g_a   [(size_t)12 * Nn * Nn];
__device__ float g_cat [Nn * DOUT];

__device__ __forceinline__ void ffma2(unsigned long long& d,
                                      unsigned long long a,
                                      unsigned long long b) {
    asm("fma.rn.f32x2 %0, %1, %2, %0;" : "+l"(d) : "l"(a), "l"(b));
}
union F2U { unsigned long long u; float2 f; };

// ---------------- K0a: concat projection weights ----------------
__global__ void copy_weights(const float* __restrict__ wq,  const float* __restrict__ bq,
                             const float* __restrict__ wkv, const float* __restrict__ bkv,
                             const float* __restrict__ wqp, const float* __restrict__ bqp,
                             const float* __restrict__ wkvp,const float* __restrict__ bkvp) {
    int idx = blockIdx.x * 256 + threadIdx.x;
    if (idx < NPROJ * CSd) {
        int r = idx / CSd, k = idx - r * CSd;
        float v;
        if      (r < 192) v = wq  [ r        * CSd + k];
        else if (r < 576) v = wkv [(r - 192) * CSd + k];
        else if (r < 720) v = wqp [(r - 576) * CSd + k];
        else              v = wkvp[(r - 720) * CSd + k];
        g_wcat[idx] = v;
    }
    if (idx < NPROJ) {
        int r = idx;
        g_bcat[r] = (r < 192) ? bq[r] : (r < 576) ? bkv[r-192]
                  : (r < 720) ? bqp[r-576] : bkvp[r-720];
    }
}

// ---------------- generic TN GEMM: C = A[M,K] * B[NC,K]^T + bias ----------------
template<int MODE>
__global__ void gemm_tn(const float* __restrict__ Aext, const float* __restrict__ Bext,
                        const float* __restrict__ biasext, float* __restrict__ Cext) {
    constexpr int KK = (MODE == 0) ? CSd : DOUT;
    constexpr int NC = (MODE == 0) ? NPROJ : CSd;
    const float* A    = (MODE == 0) ? Aext   : g_cat;
    const float* B    = (MODE == 0) ? g_wcat : Bext;
    const float* bias = (MODE == 0) ? g_bcat : biasext;
    float*       C    = (MODE == 0) ? g_proj : Cext;

    __shared__ float As[64][17];
    __shared__ float Bs[64][17];
    int t  = threadIdx.x;
    int m0 = blockIdx.y * 64, n0 = blockIdx.x * 64;
    int lr = t >> 2, lc = (t & 3) * 4;
    int ty = (t >> 4) * 4, tx = (t & 15) * 4;
    float acc[4][4] = {};

    for (int k0 = 0; k0 < KK; k0 += 16) {
        __syncthreads();
        float4 a4 = *(const float4*)(A + (size_t)(m0 + lr) * KK + k0 + lc);
        float4 b4 = *(const float4*)(B + (size_t)(n0 + lr) * KK + k0 + lc);
        As[lr][lc] = a4.x; As[lr][lc+1] = a4.y; As[lr][lc+2] = a4.z; As[lr][lc+3] = a4.w;
        Bs[lr][lc] = b4.x; Bs[lr][lc+1] = b4.y; Bs[lr][lc+2] = b4.z; Bs[lr][lc+3] = b4.w;
        __syncthreads();
        #pragma unroll
        for (int kk = 0; kk < 16; kk++) {
            float av[4], bv[4];
            #pragma unroll
            for (int r = 0; r < 4; r++) av[r] = As[ty + r][kk];
            #pragma unroll
            for (int c = 0; c < 4; c++) bv[c] = Bs[tx + c][kk];
            #pragma unroll
            for (int r = 0; r < 4; r++)
                #pragma unroll
                for (int c = 0; c < 4; c++)
                    acc[r][c] = fmaf(av[r], bv[c], acc[r][c]);
        }
    }
    #pragma unroll
    for (int r = 0; r < 4; r++)
        #pragma unroll
        for (int c = 0; c < 4; c++)
            C[(size_t)(m0 + ty + r) * NC + n0 + tx + c] = acc[r][c] + bias[n0 + tx + c];
}

// ---------------- K0b: rotate points, repack k/v into [h][j][*] ----------------
__global__ void prep_pts(const float* __restrict__ rot, const float* __restrict__ trans) {
    int n = blockIdx.x;
    const float* pr = g_proj + (size_t)n * NPROJ;
    float R[9];
    #pragma unroll
    for (int e = 0; e < 9; e++) R[e] = rot[n * 9 + e];
    float tr[3] = {trans[n*3+0], trans[n*3+1], trans[n*3+2]};

    for (int t = threadIdx.x; t < 960; t += blockDim.x) {
        if (t < 384) {                       // kv repack -> [h][j][16]
            int h = t >> 5, c = t & 31;
            float v = pr[192 + h * 32 + c];
            if (c < 16) g_kh[((size_t)h * Nn + n) * 16 + c]        = v;
            else        g_vh[((size_t)h * Nn + n) * 16 + (c - 16)] = v;
        } else if (t < 528) {                // q_pts -> [n][h][12]
            int e = t - 384;
            int g = e / 3, ax = e - g * 3;
            const float* src = pr + 576 + g * 3;
            g_qpts[n * 144 + e] =
                R[ax*3+0]*src[0] + R[ax*3+1]*src[1] + R[ax*3+2]*src[2] + tr[ax];
        } else {                             // k_pts/v_pts -> [h][j][12|24]
            int e2 = t - 528;
            int g = e2 / 3, ax = e2 - g * 3; // g = h*12 + pp
            const float* src = pr + 720 + g * 3;
            float val = R[ax*3+0]*src[0] + R[ax*3+1]*src[1] + R[ax*3+2]*src[2] + tr[ax];
            int h = g / 12, pp = g - h * 12;
            if (pp < 4) g_kph[((size_t)h * Nn + n) * 12 + pp * 3 + ax]       = val;
            else        g_vph[((size_t)h * Nn + n) * 24 + (pp - 4) * 3 + ax] = val;
        }
    }
}

// ---------------- KA: bias GEMM  g_bias[h][i][j] = sqrt(1/3)*(z[i,j].wb[h] + bb[h]) ----
// CTA = i, 128 threads; each thread owns one j-row, computes all 12 heads.
#define SMA_BYTES ((128*128 + 12*128 + 16) * 4)
__global__ __launch_bounds__(128) void bias_gemm(const float* __restrict__ z,
                                                 const float* __restrict__ w_b,
                                                 const float* __restrict__ b_b) {
    extern __shared__ float sm[];
    float* sz  = sm;                 // 128 x 128, XOR-swizzled float4 columns
    float* swb = sm + 16384;         // 12 x 128
    float* sbb = sm + 16384 + 1536;  // 12

    int i = blockIdx.x, t = threadIdx.x;
    for (int idx = t; idx < 384; idx += 128)
        ((float4*)swb)[idx] = ((const float4*)w_b)[idx];
    if (t < 12) sbb[t] = b_b[t];

    for (int j0 = 0; j0 < Nn; j0 += 128) {
        __syncthreads();
        for (int idx = t; idx < 4096; idx += 128) {
            int jj = idx >> 5, c4 = idx & 31;
            float4 v = ((const float4*)z)[((size_t)i * Nn + j0 + jj) * 32 + c4];
            ((float4*)sz)[jj * 32 + (c4 ^ (jj & 7))] = v;
        }
        __syncthreads();

        unsigned long long acc[12] = {};
        const int swz = t & 7;
        const float* zr = sz + t * 128;
        #pragma unroll 4
        for (int c4 = 0; c4 < 32; c4++) {
            ulonglong2 zz = *(const ulonglong2*)(zr + ((c4 ^ swz) << 2));
            #pragma unroll
            for (int h = 0; h < 12; h++) {
                ulonglong2 ww = *(const ulonglong2*)(swb + h * 128 + (c4 << 2));
                ffma2(acc[h], zz.x, ww.x);
                ffma2(acc[h], zz.y, ww.y);
            }
        }
        #pragma unroll
        for (int h = 0; h < 12; h++) {
            F2U u; u.u = acc[h];
            g_bias[((size_t)h * Nn + i) * Nn + j0 + t] =
                0.5773502691896258f * (u.f.x + u.f.y + sbb[h]);
        }
    }
}

// ---------------- KB: logits (no z, no smem, no barriers); 2 i's per CTA ----------
__global__ __launch_bounds__(384) void attn_logits2(const float* __restrict__ mask,
                                                    const float* __restrict__ hwraw) {
    int i0 = blockIdx.x * 2;
    int h = threadIdx.x >> 5, lane = threadIdx.x & 31;

    float q[2][16], qp[2][12];
    #pragma unroll
    for (int ii = 0; ii < 2; ii++) {
        const float4* qs = (const float4*)(g_proj + (size_t)(i0+ii) * NPROJ + h * 16);
        #pragma unroll
        for (int c = 0; c < 4; c++) {
            float4 v = qs[c];
            q[ii][c*4+0] = v.x; q[ii][c*4+1] = v.y; q[ii][c*4+2] = v.z; q[ii][c*4+3] = v.w;
        }
        const float4* ps = (const float4*)(g_qpts + (size_t)(i0+ii) * 144 + h * 12);
        #pragma unroll
        for (int c = 0; c < 3; c++) {
            float4 v = ps[c];
            qp[ii][c*4+0] = v.x; qp[ii][c*4+1] = v.y; qp[ii][c*4+2] = v.z; qp[ii][c*4+3] = v.w;
        }
    }
    float x = hwraw[h];
    float hwv = ((x > 20.f) ? x : log1pf(expf(x))) * 0.13608276348795434f;
    float mi0 = mask[i0], mi1 = mask[i0 + 1];
    const float s1 = 0.14433756729740643f;

    for (int j0 = 0; j0 < Nn; j0 += 32) {
        int j = j0 + lane;
        float mj = mask[j];
        const float4* kb = (const float4*)(g_kh + ((size_t)h * Nn + j) * 16);
        float4 k0 = kb[0], k1 = kb[1], k2 = kb[2], k3 = kb[3];
        const float4* pb = (const float4*)(g_kph + ((size_t)h * Nn + j) * 12);
        float4 p0 = pb[0], p1 = pb[1], p2 = pb[2];

        #pragma unroll
        for (int ii = 0; ii < 2; ii++) {
            float qk = 0.f;
            qk = fmaf(q[ii][0],  k0.x, qk); qk = fmaf(q[ii][1],  k0.y, qk);
            qk = fmaf(q[ii][2],  k0.z, qk); qk = fmaf(q[ii][3],  k0.w, qk);
            qk = fmaf(q[ii][4],  k1.x, qk); qk = fmaf(q[ii][5],  k1.y, qk);
            qk = fmaf(q[ii][6],  k1.z, qk); qk = fmaf(q[ii][7],  k1.w, qk);
            qk = fmaf(q[ii][8],  k2.x, qk); qk = fmaf(q[ii][9],  k2.y, qk);
            qk = fmaf(q[ii][10], k2.z, qk); qk = fmaf(q[ii][11], k2.w, qk);
            qk = fmaf(q[ii][12], k3.x, qk); qk = fmaf(q[ii][13], k3.y, qk);
            qk = fmaf(q[ii][14], k3.z, qk); qk = fmaf(q[ii][15], k3.w, qk);

            float d2 = 0.f, d;
            d = qp[ii][0]  - p0.x; d2 = fmaf(d, d, d2);
            d = qp[ii][1]  - p0.y; d2 = fmaf(d, d, d2);
            d = qp[ii][2]  - p0.z; d2 = fmaf(d, d, d2);
            d = qp[ii][3]  - p0.w; d2 = fmaf(d, d, d2);
            d = qp[ii][4]  - p1.x; d2 = fmaf(d, d, d2);
            d = qp[ii][5]  - p1.y; d2 = fmaf(d, d, d2);
            d = qp[ii][6]  - p1.z; d2 = fmaf(d, d, d2);
            d = qp[ii][7]  - p1.w; d2 = fmaf(d, d, d2);
            d = qp[ii][8]  - p2.x; d2 = fmaf(d, d, d2);
            d = qp[ii][9]  - p2.y; d2 = fmaf(d, d, d2);
            d = qp[ii][10] - p2.z; d2 = fmaf(d, d, d2);
            d = qp[ii][11] - p2.w; d2 = fmaf(d, d, d2);

            float bias = g_bias[((size_t)h * Nn + i0 + ii) * Nn + j];
            float mi = ii ? mi1 : mi0;
            g_a[((size_t)h * Nn + i0 + ii) * Nn + j] =
                qk * s1 + bias - 0.5f * hwv * d2 + INFV * (mi * mj - 1.f);
        }
    }
}

// ---------------- K2: softmax rows of g_a, in place ----------------
__global__ void softmax_rows() {
    const int i = blockIdx.x, h = blockIdx.y;
    float* row = g_a + ((size_t)h * Nn + i) * Nn;
    const int t = threadIdx.x;   // 256
    float v0 = row[t], v1 = row[t + 256], v2 = row[t + 512];

    __shared__ float sred[8];
    float m = fmaxf(v0, fmaxf(v1, v2));
    #pragma unroll
    for (int off = 16; off; off >>= 1) m = fmaxf(m, __shfl_xor_sync(0xffffffffu, m, off));
    if ((t & 31) == 0) sred[t >> 5] = m;
    __syncthreads();
    float M = sred[0];
    #pragma unroll
    for (int k = 1; k < 8; k++) M = fmaxf(M, sred[k]);
    __syncthreads();

    float e0 = __expf(v0 - M), e1 = __expf(v1 - M), e2 = __expf(v2 - M);
    float s = e0 + e1 + e2;
    #pragma unroll
    for (int off = 16; off; off >>= 1) s += __shfl_xor_sync(0xffffffffu, s, off);
    if ((t & 31) == 0) sred[t >> 5] = s;
    __syncthreads();
    float S = 0.f;
    #pragma unroll
    for (int k = 0; k < 8; k++) S += sred[k];
    float inv = 1.0f / S;
    row[t] = e0 * inv; row[t + 256] = e1 * inv; row[t + 512] = e2 * inv;
}

// ---------------- KC: o_pair = sum_j a[h,i,j] * z[i,j,:] ----------------
// CTA = i, 128 threads; warp w handles heads {3w,3w+1,3w+2}, lane = channel group.
__global__ __launch_bounds__(128) void opair(const float* __restrict__ z) {
    __shared__ float sz[32 * 128];   // row-major, row access -> conflict-free
    __shared__ float sa[12 * 32];
    int i = blockIdx.x, t = threadIdx.x, w = t >> 5, lane = t & 31;

    unsigned long long acc[3][2] = {};

    for (int j0 = 0; j0 < Nn; j0 += 32) {
        __syncthreads();
        const float4* zp = (const float4*)z + ((size_t)i * Nn + j0) * 32;
        for (int idx = t; idx < 1024; idx += 128) ((float4*)sz)[idx] = zp[idx];
        if (t < 96) {
            int hh = t >> 3, c = t & 7;
            ((float4*)sa)[t] =
                *((const float4*)(g_a + ((size_t)hh * Nn + i) * Nn + j0) + c);
        }
        __syncthreads();

        #pragma unroll 4
        for (int jj = 0; jj < 32; jj++) {
            ulonglong2 zz = *(const ulonglong2*)(sz + jj * 128 + lane * 4);
            #pragma unroll
            for (int e = 0; e < 3; e++) {
                float a = sa[(w * 3 + e) * 32 + jj];
                F2U au; au.f.x = a; au.f.y = a;
                ffma2(acc[e][0], au.u, zz.x);
                ffma2(acc[e][1], au.u, zz.y);
            }
        }
    }

    float* crow = g_cat + (size_t)i * DOUT + 576;
    #pragma unroll
    for (int e = 0; e < 3; e++) {
        F2U a0, a1; a0.u = acc[e][0]; a1.u = acc[e][1];
        float4 o = {a0.f.x, a0.f.y, a1.f.x, a1.f.y};
        *(float4*)(crow + (w * 3 + e) * 128 + lane * 4) = o;
    }
}

// ---------------- KD: o + o_pt + inverse frame + norms; 2 i's per CTA ----------
__global__ __launch_bounds__(384) void attn_out(const float* __restrict__ rot,
                                                const float* __restrict__ trans) {
    int i0 = blockIdx.x * 2;
    int h = threadIdx.x >> 5, lane = threadIdx.x & 31;

    float ao[2][16] = {};
    float ap[2][24] = {};

    for (int j0 = 0; j0 < Nn; j0 += 32) {
        int j = j0 + lane;
        const float4* vb = (const float4*)(g_vh + ((size_t)h * Nn + j) * 16);
        float4 v0 = vb[0], v1 = vb[1], v2 = vb[2], v3 = vb[3];
        const float4* pb = (const float4*)(g_vph + ((size_t)h * Nn + j) * 24);
        float4 p0 = pb[0], p1 = pb[1], p2 = pb[2], p3 = pb[3], p4 = pb[4], p5 = pb[5];

        #pragma unroll
        for (int ii = 0; ii < 2; ii++) {
            float a = g_a[((size_t)h * Nn + i0 + ii) * Nn + j];
            ao[ii][0]  = fmaf(a, v0.x, ao[ii][0]);  ao[ii][1]  = fmaf(a, v0.y, ao[ii][1]);
            ao[ii][2]  = fmaf(a, v0.z, ao[ii][2]);  ao[ii][3]  = fmaf(a, v0.w, ao[ii][3]);
            ao[ii][4]  = fmaf(a, v1.x, ao[ii][4]);  ao[ii][5]  = fmaf(a, v1.y, ao[ii][5]);
            ao[ii][6]  = fmaf(a, v1.z, ao[ii][6]);  ao[ii][7]  = fmaf(a, v1.w, ao[ii][7]);
            ao[ii][8]  = fmaf(a, v2.x, ao[ii][8]);  ao[ii][9]  = fmaf(a, v2.y, ao[ii][9]);
            ao[ii][10] = fmaf(a, v2.z, ao[ii][10]); ao[ii][11] = fmaf(a, v2.w, ao[ii][11]);
            ao[ii][12] = fmaf(a, v3.x, ao[ii][12]); ao[ii][13] = fmaf(a, v3.y, ao[ii][13]);
            ao[ii][14] = fmaf(a, v3.z, ao[ii][14]); ao[ii][15] = fmaf(a, v3.w, ao[ii][15]);

            ap[ii][0]  = fmaf(a, p0.x, ap[ii][0]);  ap[ii][1]  = fmaf(a, p0.y, ap[ii][1]);
            ap[ii][2]  = fmaf(a, p0.z, ap[ii][2]);  ap[ii][3]  = fmaf(a, p0.w, ap[ii][3]);
            ap[ii][4]  = fmaf(a, p1.x, ap[ii][4]);  ap[ii][5]  = fmaf(a, p1.y, ap[ii][5]);
            ap[ii][6]  = fmaf(a, p1.z, ap[ii][6]);  ap[ii][7]  = fmaf(a, p1.w, ap[ii][7]);
            ap[ii][8]  = fmaf(a, p2.x, ap[ii][8]);  ap[ii][9]  = fmaf(a, p2.y, ap[ii][9]);
            ap[ii][10] = fmaf(a, p2.z, ap[ii][10]); ap[ii][11] = fmaf(a, p2.w, ap[ii][11]);
            ap[ii][12] = fmaf(a, p3.x, ap[ii][12]); ap[ii][13] = fmaf(a, p3.y, ap[ii][13]);
            ap[ii][14] = fmaf(a, p3.z, ap[ii][14]); ap[ii][15] = fmaf(a, p3.w, ap[ii][15]);
            ap[ii][16] = fmaf(a, p4.x, ap[ii][16]); ap[ii][17] = fmaf(a, p4.y, ap[ii][17]);
            ap[ii][18] = fmaf(a, p4.z, ap[ii][18]); ap[ii][19] = fmaf(a, p4.w, ap[ii][19]);
            ap[ii][20] = fmaf(a, p5.x, ap[ii][20]); ap[ii][21] = fmaf(a, p5.y, ap[ii][21]);
            ap[ii][22] = fmaf(a, p5.z, ap[ii][22]); ap[ii][23] = fmaf(a, p5.w, ap[ii][23]);
        }
    }

    #pragma unroll
    for (int off = 16; off; off >>= 1) {
        #pragma unroll
        for (int ii = 0; ii < 2; ii++) {
            #pragma unroll
            for (int c = 0; c < 16; c++) ao[ii][c] += __shfl_xor_sync(0xffffffffu, ao[ii][c], off);
            #pragma unroll
            for (int e = 0; e < 24; e++) ap[ii][e] += __shfl_xor_sync(0xffffffffu, ap[ii][e], off);
        }
    }

    if (lane == 0) {
        #pragma unroll
        for (int ii = 0; ii < 2; ii++) {
            int i = i0 + ii;
            float* crow = g_cat + (size_t)i * DOUT;
            #pragma unroll
            for (int c = 0; c < 16; c++) crow[h * 16 + c] = ao[ii][c];
            float R[9];
            #pragma unroll
            for (int e = 0; e < 9; e++) R[e] = rot[i * 9 + e];
            float t0 = trans[i*3+0], t1 = trans[i*3+1], t2 = trans[i*3+2];
            #pragma unroll
            for (int p = 0; p < 8; p++) {
                float dx = ap[ii][p*3+0] - t0;
                float dy = ap[ii][p*3+1] - t1;
                float dz = ap[ii][p*3+2] - t2;
                float lx = R[0]*dx + R[3]*dy + R[6]*dz;   // R^T * d
                float ly = R[1]*dx + R[4]*dy + R[7]*dz;
                float lz = R[2]*dx + R[5]*dy + R[8]*dz;
                crow[192 + (h*8+p)*3 + 0] = lx;
                crow[192 + (h*8+p)*3 + 1] = ly;
                crow[192 + (h*8+p)*3 + 2] = lz;
                crow[480 + h*8 + p] = sqrtf(lx*lx + ly*ly + lz*lz + 1e-8f);
            }
        }
    }
}

// ---------------- host ----------------
extern "C" void kernel_launch(void* const* d_in, const int* in_sizes, int n_in,
                              void* d_out, int out_size) {
    const float* s      = (const float*)d_in[0];
    const float* z      = (const float*)d_in[1];
    const float* rot    = (const float*)d_in[2];
    const float* trans  = (const float*)d_in[3];
    const float* mask   = (const float*)d_in[4];
    const float* w_q    = (const float*)d_in[5];
    const float* b_q    = (const float*)d_in[6];
    const float* w_kv   = (const float*)d_in[7];
    const float* b_kv   = (const float*)d_in[8];
    const float* w_qp   = (const float*)d_in[9];
    const float* b_qp   = (const float*)d_in[10];
    const float* w_kvp  = (const float*)d_in[11];
    const float* b_kvp  = (const float*)d_in[12];
    const float* w_b    = (const float*)d_in[13];
    const float* b_b    = (const float*)d_in[14];
    const float* hw     = (const float*)d_in[15];
    const float* w_out  = (const float*)d_in[16];
    const float* b_out  = (const float*)d_in[17];
    float* out = (float*)d_out;

    cudaFuncSetAttribute(bias_gemm, cudaFuncAttributeMaxDynamicSharedMemorySize, SMA_BYTES);

    copy_weights<<<(NPROJ * CSd + 255) / 256, 256>>>(w_q, b_q, w_kv, b_kv,
                                                     w_qp, b_qp, w_kvp, b_kvp);
    gemm_tn<0><<<dim3(NPROJ / 64, Nn / 64), 256>>>(s, nullptr, nullptr, nullptr);
    prep_pts<<<Nn, 128>>>(rot, trans);
    bias_gemm<<<Nn, 128, SMA_BYTES>>>(z, w_b, b_b);
    attn_logits2<<<Nn / 2, 384>>>(mask, hw);
    softmax_rows<<<dim3(Nn, 12), 256>>>();
    opair<<<Nn, 128>>>(z);
    attn_out<<<Nn / 2, 384>>>(rot, trans);
    gemm_tn<1><<<dim3(CSd / 64, Nn / 64), 256>>>(nullptr, w_out, b_out, out);
}

// round 9
// speedup vs baseline: 3.2183x; 1.1348x over previous
#include <cuda_runtime.h>
#include <cmath>

#define Nn    768
#define CSd   384
#define NPROJ 1152
#define DOUT  2112
#define INFV  100000.0f

__device__ float g_proj [Nn * NPROJ];
__device__ float g_wcat [NPROJ * CSd];
__device__ float g_bcat [NPROJ];
__device__ float g_kh  [12 * Nn * 16];
__device__ float g_vh  [12 * Nn * 16];
__device__ float g_kph [12 * Nn * 12];
__device__ float g_vph [12 * Nn * 24];
__device__ float g_qpts[Nn * 144];
__device__ float g_bias[(size_t)12 * Nn * Nn];
__device__ float g_a   [(size_t)12 * Nn * Nn];
__device__ float g_cat [Nn * DOUT];
__device__ float g_part[3 * Nn * CSd];

__device__ __forceinline__ void ffma2(unsigned long long& d,
                                      unsigned long long a,
                                      unsigned long long b) {
    asm("fma.rn.f32x2 %0, %1, %2, %0;" : "+l"(d) : "l"(a), "l"(b));
}
union F2U { unsigned long long u; float2 f; };

// ---------------- K0a: concat projection weights ----------------
__global__ void copy_weights(const float* __restrict__ wq,  const float* __restrict__ bq,
                             const float* __restrict__ wkv, const float* __restrict__ bkv,
                             const float* __restrict__ wqp, const float* __restrict__ bqp,
                             const float* __restrict__ wkvp,const float* __restrict__ bkvp) {
    int idx = blockIdx.x * 256 + threadIdx.x;
    if (idx < NPROJ * CSd) {
        int r = idx / CSd, k = idx - r * CSd;
        float v;
        if      (r < 192) v = wq  [ r        * CSd + k];
        else if (r < 576) v = wkv [(r - 192) * CSd + k];
        else if (r < 720) v = wqp [(r - 576) * CSd + k];
        else              v = wkvp[(r - 720) * CSd + k];
        g_wcat[idx] = v;
    }
    if (idx < NPROJ) {
        int r = idx;
        g_bcat[r] = (r < 192) ? bq[r] : (r < 576) ? bkv[r-192]
                  : (r < 720) ? bqp[r-576] : bkvp[r-720];
    }
}

// ---------------- projection GEMM: g_proj = s[768,384] * g_wcat[1152,384]^T + b ------
__global__ void gemm_proj(const float* __restrict__ A) {
    constexpr int KK = CSd;
    constexpr int NC = NPROJ;
    const float* B    = g_wcat;
    const float* bias = g_bcat;
    float*       C    = g_proj;

    __shared__ float As[64][17];
    __shared__ float Bs[64][17];
    int t  = threadIdx.x;
    int m0 = blockIdx.y * 64, n0 = blockIdx.x * 64;
    int lr = t >> 2, lc = (t & 3) * 4;
    int ty = (t >> 4) * 4, tx = (t & 15) * 4;
    float acc[4][4] = {};

    for (int k0 = 0; k0 < KK; k0 += 16) {
        __syncthreads();
        float4 a4 = *(const float4*)(A + (size_t)(m0 + lr) * KK + k0 + lc);
        float4 b4 = *(const float4*)(B + (size_t)(n0 + lr) * KK + k0 + lc);
        As[lr][lc] = a4.x; As[lr][lc+1] = a4.y; As[lr][lc+2] = a4.z; As[lr][lc+3] = a4.w;
        Bs[lr][lc] = b4.x; Bs[lr][lc+1] = b4.y; Bs[lr][lc+2] = b4.z; Bs[lr][lc+3] = b4.w;
        __syncthreads();
        #pragma unroll
        for (int kk = 0; kk < 16; kk++) {
            float av[4], bv[4];
            #pragma unroll
            for (int r = 0; r < 4; r++) av[r] = As[ty + r][kk];
            #pragma unroll
            for (int c = 0; c < 4; c++) bv[c] = Bs[tx + c][kk];
            #pragma unroll
            for (int r = 0; r < 4; r++)
                #pragma unroll
                for (int c = 0; c < 4; c++)
                    acc[r][c] = fmaf(av[r], bv[c], acc[r][c]);
        }
    }
    #pragma unroll
    for (int r = 0; r < 4; r++)
        #pragma unroll
        for (int c = 0; c < 4; c++)
            C[(size_t)(m0 + ty + r) * NC + n0 + tx + c] = acc[r][c] + bias[n0 + tx + c];
}

// ---------------- output GEMM, K split 3: g_part[kc] = g_cat[:,kc] * w_out[:,kc]^T ---
__global__ void gemm_out_split(const float* __restrict__ w_out) {
    constexpr int KCH = DOUT / 3;    // 704
    const float* A = g_cat;
    const float* B = w_out;
    int kc = blockIdx.z;
    float* C = g_part + (size_t)kc * Nn * CSd;

    __shared__ float As[64][17];
    __shared__ float Bs[64][17];
    int t  = threadIdx.x;
    int m0 = blockIdx.y * 64, n0 = blockIdx.x * 64;
    int lr = t >> 2, lc = (t & 3) * 4;
    int ty = (t >> 4) * 4, tx = (t & 15) * 4;
    float acc[4][4] = {};

    for (int k0 = kc * KCH; k0 < (kc + 1) * KCH; k0 += 16) {
        __syncthreads();
        float4 a4 = *(const float4*)(A + (size_t)(m0 + lr) * DOUT + k0 + lc);
        float4 b4 = *(const float4*)(B + (size_t)(n0 + lr) * DOUT + k0 + lc);
        As[lr][lc] = a4.x; As[lr][lc+1] = a4.y; As[lr][lc+2] = a4.z; As[lr][lc+3] = a4.w;
        Bs[lr][lc] = b4.x; Bs[lr][lc+1] = b4.y; Bs[lr][lc+2] = b4.z; Bs[lr][lc+3] = b4.w;
        __syncthreads();
        #pragma unroll
        for (int kk = 0; kk < 16; kk++) {
            float av[4], bv[4];
            #pragma unroll
            for (int r = 0; r < 4; r++) av[r] = As[ty + r][kk];
            #pragma unroll
            for (int c = 0; c < 4; c++) bv[c] = Bs[tx + c][kk];
            #pragma unroll
            for (int r = 0; r < 4; r++)
                #pragma unroll
                for (int c = 0; c < 4; c++)
                    acc[r][c] = fmaf(av[r], bv[c], acc[r][c]);
        }
    }
    #pragma unroll
    for (int r = 0; r < 4; r++)
        #pragma unroll
        for (int c = 0; c < 4; c++)
            C[(size_t)(m0 + ty + r) * CSd + n0 + tx + c] = acc[r][c];
}

__global__ void gemm_out_combine(const float* __restrict__ b_out, float* __restrict__ out) {
    int idx = blockIdx.x * 256 + threadIdx.x;
    if (idx < Nn * CSd) {
        int c = idx % CSd;
        out[idx] = g_part[idx] + g_part[idx + Nn * CSd] + g_part[idx + 2 * Nn * CSd]
                 + b_out[c];
    }
}

// ---------------- K0b: rotate points, repack k/v into [h][j][*] ----------------
__global__ void prep_pts(const float* __restrict__ rot, const float* __restrict__ trans) {
    int n = blockIdx.x;
    const float* pr = g_proj + (size_t)n * NPROJ;
    float R[9];
    #pragma unroll
    for (int e = 0; e < 9; e++) R[e] = rot[n * 9 + e];
    float tr[3] = {trans[n*3+0], trans[n*3+1], trans[n*3+2]};

    for (int t = threadIdx.x; t < 960; t += blockDim.x) {
        if (t < 384) {
            int h = t >> 5, c = t & 31;
            float v = pr[192 + h * 32 + c];
            if (c < 16) g_kh[((size_t)h * Nn + n) * 16 + c]        = v;
            else        g_vh[((size_t)h * Nn + n) * 16 + (c - 16)] = v;
        } else if (t < 528) {
            int e = t - 384;
            int g = e / 3, ax = e - g * 3;
            const float* src = pr + 576 + g * 3;
            g_qpts[n * 144 + e] =
                R[ax*3+0]*src[0] + R[ax*3+1]*src[1] + R[ax*3+2]*src[2] + tr[ax];
        } else {
            int e2 = t - 528;
            int g = e2 / 3, ax = e2 - g * 3;
            const float* src = pr + 720 + g * 3;
            float val = R[ax*3+0]*src[0] + R[ax*3+1]*src[1] + R[ax*3+2]*src[2] + tr[ax];
            int h = g / 12, pp = g - h * 12;
            if (pp < 4) g_kph[((size_t)h * Nn + n) * 12 + pp * 3 + ax]       = val;
            else        g_vph[((size_t)h * Nn + n) * 24 + (pp - 4) * 3 + ax] = val;
        }
    }
}

// ---------------- KA: bias GEMM  g_bias[h][i][j] = sqrt(1/3)*(z[i,j].wb[h] + bb[h]) ----
// grid (12 j-tiles, 768 i), 256 threads: g = t>>6 channel-group, jl = t&63 row.
#define SMA_BYTES (12816 * 4)
__global__ __launch_bounds__(256) void bias_gemm(const float* __restrict__ z,
                                                 const float* __restrict__ w_b,
                                                 const float* __restrict__ b_b) {
    extern __shared__ float sm[];
    float* sz   = sm;            // 64 x 128, full XOR swizzle on float4 cols
    float* swb  = sm + 8192;     // 12 x 128
    float* sbb  = sm + 9728;     // 12
    float* part = sm + 9744;     // [4][12][64]

    int jt = blockIdx.x, i = blockIdx.y;
    int j0 = jt * 64;
    int t = threadIdx.x;
    int g = t >> 6, jl = t & 63;

    for (int idx = t; idx < 384; idx += 256)
        ((float4*)swb)[idx] = ((const float4*)w_b)[idx];
    if (t < 12) sbb[t] = b_b[t];

    for (int idx = t; idx < 2048; idx += 256) {
        int jj = idx >> 5, c4 = idx & 31;
        float4 v = ((const float4*)z)[((size_t)i * Nn + j0 + jj) * 32 + c4];
        ((float4*)sz)[jj * 32 + (c4 ^ (jj & 31))] = v;
    }
    __syncthreads();

    unsigned long long acc[12] = {};
    const int sw = jl & 31;
    const float* zr = sz + jl * 128;
    #pragma unroll
    for (int cc = 0; cc < 8; cc++) {
        int c4 = g * 8 + cc;
        ulonglong2 zz = *(const ulonglong2*)(zr + ((c4 ^ sw) << 2));
        #pragma unroll
        for (int h = 0; h < 12; h++) {
            ulonglong2 ww = *(const ulonglong2*)(swb + h * 128 + (c4 << 2));
            ffma2(acc[h], zz.x, ww.x);
            ffma2(acc[h], zz.y, ww.y);
        }
    }
    #pragma unroll
    for (int h = 0; h < 12; h++) {
        F2U u; u.u = acc[h];
        part[(g * 12 + h) * 64 + jl] = u.f.x + u.f.y;
    }
    __syncthreads();

    if (t < 64) {
        #pragma unroll
        for (int h = 0; h < 12; h++) {
            float s = part[h * 64 + t] + part[(12 + h) * 64 + t]
                    + part[(24 + h) * 64 + t] + part[(36 + h) * 64 + t];
            g_bias[((size_t)h * Nn + i) * Nn + j0 + t] =
                0.5773502691896258f * (s + sbb[h]);
        }
    }
}

// ---------------- KB: logits (no z, no smem, no barriers); 2 i's per CTA ----------
__global__ __launch_bounds__(384) void attn_logits2(const float* __restrict__ mask,
                                                    const float* __restrict__ hwraw) {
    int i0 = blockIdx.x * 2;
    int h = threadIdx.x >> 5, lane = threadIdx.x & 31;

    float q[2][16], qp[2][12];
    #pragma unroll
    for (int ii = 0; ii < 2; ii++) {
        const float4* qs = (const float4*)(g_proj + (size_t)(i0+ii) * NPROJ + h * 16);
        #pragma unroll
        for (int c = 0; c < 4; c++) {
            float4 v = qs[c];
            q[ii][c*4+0] = v.x; q[ii][c*4+1] = v.y; q[ii][c*4+2] = v.z; q[ii][c*4+3] = v.w;
        }
        const float4* ps = (const float4*)(g_qpts + (size_t)(i0+ii) * 144 + h * 12);
        #pragma unroll
        for (int c = 0; c < 3; c++) {
            float4 v = ps[c];
            qp[ii][c*4+0] = v.x; qp[ii][c*4+1] = v.y; qp[ii][c*4+2] = v.z; qp[ii][c*4+3] = v.w;
        }
    }
    float x = hwraw[h];
    float hwv = ((x > 20.f) ? x : log1pf(expf(x))) * 0.13608276348795434f;
    float mi0 = mask[i0], mi1 = mask[i0 + 1];
    const float s1 = 0.14433756729740643f;

    for (int j0 = 0; j0 < Nn; j0 += 32) {
        int j = j0 + lane;
        float mj = mask[j];
        const float4* kb = (const float4*)(g_kh + ((size_t)h * Nn + j) * 16);
        float4 k0 = kb[0], k1 = kb[1], k2 = kb[2], k3 = kb[3];
        const float4* pb = (const float4*)(g_kph + ((size_t)h * Nn + j) * 12);
        float4 p0 = pb[0], p1 = pb[1], p2 = pb[2];

        #pragma unroll
        for (int ii = 0; ii < 2; ii++) {
            float qk = 0.f;
            qk = fmaf(q[ii][0],  k0.x, qk); qk = fmaf(q[ii][1],  k0.y, qk);
            qk = fmaf(q[ii][2],  k0.z, qk); qk = fmaf(q[ii][3],  k0.w, qk);
            qk = fmaf(q[ii][4],  k1.x, qk); qk = fmaf(q[ii][5],  k1.y, qk);
            qk = fmaf(q[ii][6],  k1.z, qk); qk = fmaf(q[ii][7],  k1.w, qk);
            qk = fmaf(q[ii][8],  k2.x, qk); qk = fmaf(q[ii][9],  k2.y, qk);
            qk = fmaf(q[ii][10], k2.z, qk); qk = fmaf(q[ii][11], k2.w, qk);
            qk = fmaf(q[ii][12], k3.x, qk); qk = fmaf(q[ii][13], k3.y, qk);
            qk = fmaf(q[ii][14], k3.z, qk); qk = fmaf(q[ii][15], k3.w, qk);

            float d2 = 0.f, d;
            d = qp[ii][0]  - p0.x; d2 = fmaf(d, d, d2);
            d = qp[ii][1]  - p0.y; d2 = fmaf(d, d, d2);
            d = qp[ii][2]  - p0.z; d2 = fmaf(d, d, d2);
            d = qp[ii][3]  - p0.w; d2 = fmaf(d, d, d2);
            d = qp[ii][4]  - p1.x; d2 = fmaf(d, d, d2);
            d = qp[ii][5]  - p1.y; d2 = fmaf(d, d, d2);
            d = qp[ii][6]  - p1.z; d2 = fmaf(d, d, d2);
            d = qp[ii][7]  - p1.w; d2 = fmaf(d, d, d2);
            d = qp[ii][8]  - p2.x; d2 = fmaf(d, d, d2);
            d = qp[ii][9]  - p2.y; d2 = fmaf(d, d, d2);
            d = qp[ii][10] - p2.z; d2 = fmaf(d, d, d2);
            d = qp[ii][11] - p2.w; d2 = fmaf(d, d, d2);

            float bias = g_bias[((size_t)h * Nn + i0 + ii) * Nn + j];
            float mi = ii ? mi1 : mi0;
            g_a[((size_t)h * Nn + i0 + ii) * Nn + j] =
                qk * s1 + bias - 0.5f * hwv * d2 + INFV * (mi * mj - 1.f);
        }
    }
}

// ---------------- K2: softmax rows of g_a, in place ----------------
__global__ void softmax_rows() {
    const int i = blockIdx.x, h = blockIdx.y;
    float* row = g_a + ((size_t)h * Nn + i) * Nn;
    const int t = threadIdx.x;   // 256
    float v0 = row[t], v1 = row[t + 256], v2 = row[t + 512];

    __shared__ float sred[8];
    float m = fmaxf(v0, fmaxf(v1, v2));
    #pragma unroll
    for (int off = 16; off; off >>= 1) m = fmaxf(m, __shfl_xor_sync(0xffffffffu, m, off));
    if ((t & 31) == 0) sred[t >> 5] = m;
    __syncthreads();
    float M = sred[0];
    #pragma unroll
    for (int k = 1; k < 8; k++) M = fmaxf(M, sred[k]);
    __syncthreads();

    float e0 = __expf(v0 - M), e1 = __expf(v1 - M), e2 = __expf(v2 - M);
    float s = e0 + e1 + e2;
    #pragma unroll
    for (int off = 16; off; off >>= 1) s += __shfl_xor_sync(0xffffffffu, s, off);
    if ((t & 31) == 0) sred[t >> 5] = s;
    __syncthreads();
    float S = 0.f;
    #pragma unroll
    for (int k = 0; k < 8; k++) S += sred[k];
    float inv = 1.0f / S;
    row[t] = e0 * inv; row[t + 256] = e1 * inv; row[t + 512] = e2 * inv;
}

// ---------------- KC: o_pair, channel-split: grid (2 chalf, 768 i), 128 thr ------
__global__ __launch_bounds__(128) void opair(const float* __restrict__ z) {
    __shared__ float sz[32 * 64];    // 32 j x 64 ch (this CTA's half)
    __shared__ float sa[12 * 32];
    int chalf = blockIdx.x, i = blockIdx.y;
    int t = threadIdx.x, w = t >> 5, lane = t & 31;

    unsigned long long acc[3] = {};

    for (int j0 = 0; j0 < Nn; j0 += 32) {
        __syncthreads();
        for (int idx = t; idx < 512; idx += 128) {
            int jj = idx >> 4, c4 = idx & 15;
            ((float4*)sz)[jj * 16 + c4] =
                ((const float4*)z)[((size_t)i * Nn + j0 + jj) * 32 + chalf * 16 + c4];
        }
        if (t < 96) {
            int hh = t >> 3, c = t & 7;
            ((float4*)sa)[t] =
                *((const float4*)(g_a + ((size_t)hh * Nn + i) * Nn + j0) + c);
        }
        __syncthreads();

        #pragma unroll
        for (int jj4 = 0; jj4 < 8; jj4++) {
            float4 a0 = ((const float4*)(sa + (w * 3 + 0) * 32))[jj4];
            float4 a1 = ((const float4*)(sa + (w * 3 + 1) * 32))[jj4];
            float4 a2 = ((const float4*)(sa + (w * 3 + 2) * 32))[jj4];
            float a0v[4] = {a0.x, a0.y, a0.z, a0.w};
            float a1v[4] = {a1.x, a1.y, a1.z, a1.w};
            float a2v[4] = {a2.x, a2.y, a2.z, a2.w};
            #pragma unroll
            for (int sub = 0; sub < 4; sub++) {
                int jj = jj4 * 4 + sub;
                unsigned long long zz =
                    *(const unsigned long long*)(sz + jj * 64 + lane * 2);
                F2U u0, u1, u2;
                u0.f.x = a0v[sub]; u0.f.y = a0v[sub];
                u1.f.x = a1v[sub]; u1.f.y = a1v[sub];
                u2.f.x = a2v[sub]; u2.f.y = a2v[sub];
                ffma2(acc[0], u0.u, zz);
                ffma2(acc[1], u1.u, zz);
                ffma2(acc[2], u2.u, zz);
            }
        }
    }

    float* crow = g_cat + (size_t)i * DOUT + 576 + chalf * 64;
    #pragma unroll
    for (int e = 0; e < 3; e++) {
        F2U u; u.u = acc[e];
        *(float2*)(crow + (w * 3 + e) * 128 + lane * 2) = u.f;
    }
}

// ---------------- KD: o + o_pt + inverse frame + norms; 2 i's per CTA ----------
__global__ __launch_bounds__(384) void attn_out(const float* __restrict__ rot,
                                                const float* __restrict__ trans) {
    int i0 = blockIdx.x * 2;
    int h = threadIdx.x >> 5, lane = threadIdx.x & 31;

    float ao[2][16] = {};
    float ap[2][24] = {};

    for (int j0 = 0; j0 < Nn; j0 += 32) {
        int j = j0 + lane;
        const float4* vb = (const float4*)(g_vh + ((size_t)h * Nn + j) * 16);
        float4 v0 = vb[0], v1 = vb[1], v2 = vb[2], v3 = vb[3];
        const float4* pb = (const float4*)(g_vph + ((size_t)h * Nn + j) * 24);
        float4 p0 = pb[0], p1 = pb[1], p2 = pb[2], p3 = pb[3], p4 = pb[4], p5 = pb[5];

        #pragma unroll
        for (int ii = 0; ii < 2; ii++) {
            float a = g_a[((size_t)h * Nn + i0 + ii) * Nn + j];
            ao[ii][0]  = fmaf(a, v0.x, ao[ii][0]);  ao[ii][1]  = fmaf(a, v0.y, ao[ii][1]);
            ao[ii][2]  = fmaf(a, v0.z, ao[ii][2]);  ao[ii][3]  = fmaf(a, v0.w, ao[ii][3]);
            ao[ii][4]  = fmaf(a, v1.x, ao[ii][4]);  ao[ii][5]  = fmaf(a, v1.y, ao[ii][5]);
            ao[ii][6]  = fmaf(a, v1.z, ao[ii][6]);  ao[ii][7]  = fmaf(a, v1.w, ao[ii][7]);
            ao[ii][8]  = fmaf(a, v2.x, ao[ii][8]);  ao[ii][9]  = fmaf(a, v2.y, ao[ii][9]);
            ao[ii][10] = fmaf(a, v2.z, ao[ii][10]); ao[ii][11] = fmaf(a, v2.w, ao[ii][11]);
            ao[ii][12] = fmaf(a, v3.x, ao[ii][12]); ao[ii][13] = fmaf(a, v3.y, ao[ii][13]);
            ao[ii][14] = fmaf(a, v3.z, ao[ii][14]); ao[ii][15] = fmaf(a, v3.w, ao[ii][15]);

            ap[ii][0]  = fmaf(a, p0.x, ap[ii][0]);  ap[ii][1]  = fmaf(a, p0.y, ap[ii][1]);
            ap[ii][2]  = fmaf(a, p0.z, ap[ii][2]);  ap[ii][3]  = fmaf(a, p0.w, ap[ii][3]);
            ap[ii][4]  = fmaf(a, p1.x, ap[ii][4]);  ap[ii][5]  = fmaf(a, p1.y, ap[ii][5]);
            ap[ii][6]  = fmaf(a, p1.z, ap[ii][6]);  ap[ii][7]  = fmaf(a, p1.w, ap[ii][7]);
            ap[ii][8]  = fmaf(a, p2.x, ap[ii][8]);  ap[ii][9]  = fmaf(a, p2.y, ap[ii][9]);
            ap[ii][10] = fmaf(a, p2.z, ap[ii][10]); ap[ii][11] = fmaf(a, p2.w, ap[ii][11]);
            ap[ii][12] = fmaf(a, p3.x, ap[ii][12]); ap[ii][13] = fmaf(a, p3.y, ap[ii][13]);
            ap[ii][14] = fmaf(a, p3.z, ap[ii][14]); ap[ii][15] = fmaf(a, p3.w, ap[ii][15]);
            ap[ii][16] = fmaf(a, p4.x, ap[ii][16]); ap[ii][17] = fmaf(a, p4.y, ap[ii][17]);
            ap[ii][18] = fmaf(a, p4.z, ap[ii][18]); ap[ii][19] = fmaf(a, p4.w, ap[ii][19]);
            ap[ii][20] = fmaf(a, p5.x, ap[ii][20]); ap[ii][21] = fmaf(a, p5.y, ap[ii][21]);
            ap[ii][22] = fmaf(a, p5.z, ap[ii][22]); ap[ii][23] = fmaf(a, p5.w, ap[ii][23]);
        }
    }

    #pragma unroll
    for (int off = 16; off; off >>= 1) {
        #pragma unroll
        for (int ii = 0; ii < 2; ii++) {
            #pragma unroll
            for (int c = 0; c < 16; c++) ao[ii][c] += __shfl_xor_sync(0xffffffffu, ao[ii][c], off);
            #pragma unroll
            for (int e = 0; e < 24; e++) ap[ii][e] += __shfl_xor_sync(0xffffffffu, ap[ii][e], off);
        }
    }

    if (lane == 0) {
        #pragma unroll
        for (int ii = 0; ii < 2; ii++) {
            int i = i0 + ii;
            float* crow = g_cat + (size_t)i * DOUT;
            #pragma unroll
            for (int c = 0; c < 16; c++) crow[h * 16 + c] = ao[ii][c];
            float R[9];
            #pragma unroll
            for (int e = 0; e < 9; e++) R[e] = rot[i * 9 + e];
            float t0 = trans[i*3+0], t1 = trans[i*3+1], t2 = trans[i*3+2];
            #pragma unroll
            for (int p = 0; p < 8; p++) {
                float dx = ap[ii][p*3+0] - t0;
                float dy = ap[ii][p*3+1] - t1;
                float dz = ap[ii][p*3+2] - t2;
                float lx = R[0]*dx + R[3]*dy + R[6]*dz;
                float ly = R[1]*dx + R[4]*dy + R[7]*dz;
                float lz = R[2]*dx + R[5]*dy + R[8]*dz;
                crow[192 + (h*8+p)*3 + 0] = lx;
                crow[192 + (h*8+p)*3 + 1] = ly;
                crow[192 + (h*8+p)*3 + 2] = lz;
                crow[480 + h*8 + p] = sqrtf(lx*lx + ly*ly + lz*lz + 1e-8f);
            }
        }
    }
}

// ---------------- host ----------------
extern "C" void kernel_launch(void* const* d_in, const int* in_sizes, int n_in,
                              void* d_out, int out_size) {
    const float* s      = (const float*)d_in[0];
    const float* z      = (const float*)d_in[1];
    const float* rot    = (const float*)d_in[2];
    const float* trans  = (const float*)d_in[3];
    const float* mask   = (const float*)d_in[4];
    const float* w_q    = (const float*)d_in[5];
    const float* b_q    = (const float*)d_in[6];
    const float* w_kv   = (const float*)d_in[7];
    const float* b_kv   = (const float*)d_in[8];
    const float* w_qp   = (const float*)d_in[9];
    const float* b_qp   = (const float*)d_in[10];
    const float* w_kvp  = (const float*)d_in[11];
    const float* b_kvp  = (const float*)d_in[12];
    const float* w_b    = (const float*)d_in[13];
    const float* b_b    = (const float*)d_in[14];
    const float* hw     = (const float*)d_in[15];
    const float* w_out  = (const float*)d_in[16];
    const float* b_out  = (const float*)d_in[17];
    float* out = (float*)d_out;

    cudaFuncSetAttribute(bias_gemm, cudaFuncAttributeMaxDynamicSharedMemorySize, SMA_BYTES);

    copy_weights<<<(NPROJ * CSd + 255) / 256, 256>>>(w_q, b_q, w_kv, b_kv,
                                                     w_qp, b_qp, w_kvp, b_kvp);
    gemm_proj<<<dim3(NPROJ / 64, Nn / 64), 256>>>(s);
    prep_pts<<<Nn, 128>>>(rot, trans);
    bias_gemm<<<dim3(12, Nn), 256, SMA_BYTES>>>(z, w_b, b_b);
    attn_logits2<<<Nn / 2, 384>>>(mask, hw);
    softmax_rows<<<dim3(Nn, 12), 256>>>();
    opair<<<dim3(2, Nn), 128>>>(z);
    attn_out<<<Nn / 2, 384>>>(rot, trans);
    gemm_out_split<<<dim3(CSd / 64, Nn / 64, 3), 256>>>(w_out);
    gemm_out_combine<<<(Nn * CSd + 255) / 256, 256>>>(b_out, out);
}

// round 10
// speedup vs baseline: 3.4478x; 1.0713x over previous
#include <cuda_runtime.h>
#include <cmath>

#define Nn    768
#define CSd   384
#define NPROJ 1152
#define DOUT  2112
#define INFV  100000.0f

__device__ float g_proj [Nn * NPROJ];
__device__ float g_wcat [NPROJ * CSd];
__device__ float g_bcat [NPROJ];
__device__ float g_kh  [12 * Nn * 16];
__device__ float g_vh  [12 * Nn * 16];
__device__ float g_kph [12 * Nn * 12];
__device__ float g_vph [12 * Nn * 24];
__device__ float g_qpts[Nn * 144];
__device__ float g_bias[(size_t)12 * Nn * Nn];
__device__ float g_a   [(size_t)12 * Nn * Nn];
__device__ float g_cat [Nn * DOUT];
__device__ float g_part[3 * Nn * CSd];

__device__ __forceinline__ void ffma2(unsigned long long& d,
                                      unsigned long long a,
                                      unsigned long long b) {
    asm("fma.rn.f32x2 %0, %1, %2, %0;" : "+l"(d) : "l"(a), "l"(b));
}
union F2U { unsigned long long u; float2 f; };

// ---------------- K0a: concat projection weights ----------------
__global__ void copy_weights(const float* __restrict__ wq,  const float* __restrict__ bq,
                             const float* __restrict__ wkv, const float* __restrict__ bkv,
                             const float* __restrict__ wqp, const float* __restrict__ bqp,
                             const float* __restrict__ wkvp,const float* __restrict__ bkvp) {
    int idx = blockIdx.x * 256 + threadIdx.x;
    if (idx < NPROJ * CSd) {
        int r = idx / CSd, k = idx - r * CSd;
        float v;
        if      (r < 192) v = wq  [ r        * CSd + k];
        else if (r < 576) v = wkv [(r - 192) * CSd + k];
        else if (r < 720) v = wqp [(r - 576) * CSd + k];
        else              v = wkvp[(r - 720) * CSd + k];
        g_wcat[idx] = v;
    }
    if (idx < NPROJ) {
        int r = idx;
        g_bcat[r] = (r < 192) ? bq[r] : (r < 576) ? bkv[r-192]
                  : (r < 720) ? bqp[r-576] : bkvp[r-720];
    }
}

// ---------------- projection GEMM ----------------
__global__ void gemm_proj(const float* __restrict__ A) {
    constexpr int KK = CSd;
    constexpr int NC = NPROJ;
    const float* B    = g_wcat;
    const float* bias = g_bcat;
    float*       C    = g_proj;

    __shared__ float As[64][17];
    __shared__ float Bs[64][17];
    int t  = threadIdx.x;
    int m0 = blockIdx.y * 64, n0 = blockIdx.x * 64;
    int lr = t >> 2, lc = (t & 3) * 4;
    int ty = (t >> 4) * 4, tx = (t & 15) * 4;
    float acc[4][4] = {};

    for (int k0 = 0; k0 < KK; k0 += 16) {
        __syncthreads();
        float4 a4 = *(const float4*)(A + (size_t)(m0 + lr) * KK + k0 + lc);
        float4 b4 = *(const float4*)(B + (size_t)(n0 + lr) * KK + k0 + lc);
        As[lr][lc] = a4.x; As[lr][lc+1] = a4.y; As[lr][lc+2] = a4.z; As[lr][lc+3] = a4.w;
        Bs[lr][lc] = b4.x; Bs[lr][lc+1] = b4.y; Bs[lr][lc+2] = b4.z; Bs[lr][lc+3] = b4.w;
        __syncthreads();
        #pragma unroll
        for (int kk = 0; kk < 16; kk++) {
            float av[4], bv[4];
            #pragma unroll
            for (int r = 0; r < 4; r++) av[r] = As[ty + r][kk];
            #pragma unroll
            for (int c = 0; c < 4; c++) bv[c] = Bs[tx + c][kk];
            #pragma unroll
            for (int r = 0; r < 4; r++)
                #pragma unroll
                for (int c = 0; c < 4; c++)
                    acc[r][c] = fmaf(av[r], bv[c], acc[r][c]);
        }
    }
    #pragma unroll
    for (int r = 0; r < 4; r++)
        #pragma unroll
        for (int c = 0; c < 4; c++)
            C[(size_t)(m0 + ty + r) * NC + n0 + tx + c] = acc[r][c] + bias[n0 + tx + c];
}

// ---------------- output GEMM, K split 3 ----------------
__global__ void gemm_out_split(const float* __restrict__ w_out) {
    constexpr int KCH = DOUT / 3;    // 704
    const float* A = g_cat;
    const float* B = w_out;
    int kc = blockIdx.z;
    float* C = g_part + (size_t)kc * Nn * CSd;

    __shared__ float As[64][17];
    __shared__ float Bs[64][17];
    int t  = threadIdx.x;
    int m0 = blockIdx.y * 64, n0 = blockIdx.x * 64;
    int lr = t >> 2, lc = (t & 3) * 4;
    int ty = (t >> 4) * 4, tx = (t & 15) * 4;
    float acc[4][4] = {};

    for (int k0 = kc * KCH; k0 < (kc + 1) * KCH; k0 += 16) {
        __syncthreads();
        float4 a4 = *(const float4*)(A + (size_t)(m0 + lr) * DOUT + k0 + lc);
        float4 b4 = *(const float4*)(B + (size_t)(n0 + lr) * DOUT + k0 + lc);
        As[lr][lc] = a4.x; As[lr][lc+1] = a4.y; As[lr][lc+2] = a4.z; As[lr][lc+3] = a4.w;
        Bs[lr][lc] = b4.x; Bs[lr][lc+1] = b4.y; Bs[lr][lc+2] = b4.z; Bs[lr][lc+3] = b4.w;
        __syncthreads();
        #pragma unroll
        for (int kk = 0; kk < 16; kk++) {
            float av[4], bv[4];
            #pragma unroll
            for (int r = 0; r < 4; r++) av[r] = As[ty + r][kk];
            #pragma unroll
            for (int c = 0; c < 4; c++) bv[c] = Bs[tx + c][kk];
            #pragma unroll
            for (int r = 0; r < 4; r++)
                #pragma unroll
                for (int c = 0; c < 4; c++)
                    acc[r][c] = fmaf(av[r], bv[c], acc[r][c]);
        }
    }
    #pragma unroll
    for (int r = 0; r < 4; r++)
        #pragma unroll
        for (int c = 0; c < 4; c++)
            C[(size_t)(m0 + ty + r) * CSd + n0 + tx + c] = acc[r][c];
}

__global__ void gemm_out_combine(const float* __restrict__ b_out, float* __restrict__ out) {
    int idx = blockIdx.x * 256 + threadIdx.x;
    if (idx < Nn * CSd) {
        int c = idx % CSd;
        out[idx] = g_part[idx] + g_part[idx + Nn * CSd] + g_part[idx + 2 * Nn * CSd]
                 + b_out[c];
    }
}

// ---------------- K0b: rotate points, repack k/v into [h][j][*] ----------------
__global__ void prep_pts(const float* __restrict__ rot, const float* __restrict__ trans) {
    int n = blockIdx.x;
    const float* pr = g_proj + (size_t)n * NPROJ;
    float R[9];
    #pragma unroll
    for (int e = 0; e < 9; e++) R[e] = rot[n * 9 + e];
    float tr[3] = {trans[n*3+0], trans[n*3+1], trans[n*3+2]};

    for (int t = threadIdx.x; t < 960; t += blockDim.x) {
        if (t < 384) {
            int h = t >> 5, c = t & 31;
            float v = pr[192 + h * 32 + c];
            if (c < 16) g_kh[((size_t)h * Nn + n) * 16 + c]        = v;
            else        g_vh[((size_t)h * Nn + n) * 16 + (c - 16)] = v;
        } else if (t < 528) {
            int e = t - 384;
            int g = e / 3, ax = e - g * 3;
            const float* src = pr + 576 + g * 3;
            g_qpts[n * 144 + e] =
                R[ax*3+0]*src[0] + R[ax*3+1]*src[1] + R[ax*3+2]*src[2] + tr[ax];
        } else {
            int e2 = t - 528;
            int g = e2 / 3, ax = e2 - g * 3;
            const float* src = pr + 720 + g * 3;
            float val = R[ax*3+0]*src[0] + R[ax*3+1]*src[1] + R[ax*3+2]*src[2] + tr[ax];
            int h = g / 12, pp = g - h * 12;
            if (pp < 4) g_kph[((size_t)h * Nn + n) * 12 + pp * 3 + ax]       = val;
            else        g_vph[((size_t)h * Nn + n) * 24 + (pp - 4) * 3 + ax] = val;
        }
    }
}

// ---------------- KA: bias GEMM, 2 i's per CTA (amortize w_b LDS) ----------------
// grid (12 jt, 384 ip), 256 threads: g = t>>6 channel-group, jl = t&63 row.
// smem floats: sz0 8192 | sz1 8192 | swb 1536 | sbb 12 (+4 pad) | part 2*3072
#define SMA_BYTES (24096 * 4)
__global__ __launch_bounds__(256) void bias_gemm(const float* __restrict__ z,
                                                 const float* __restrict__ w_b,
                                                 const float* __restrict__ b_b) {
    extern __shared__ float sm[];
    float* sz0  = sm;
    float* sz1  = sm + 8192;
    float* swb  = sm + 16384;
    float* sbb  = sm + 17920;
    float* part = sm + 17936;     // [2][4][12][64]

    int jt = blockIdx.x, ip = blockIdx.y;
    int j0 = jt * 64, i0 = ip * 2;
    int t = threadIdx.x;
    int g = t >> 6, jl = t & 63;

    for (int idx = t; idx < 384; idx += 256)
        ((float4*)swb)[idx] = ((const float4*)w_b)[idx];
    if (t < 12) sbb[t] = b_b[t];

    for (int idx = t; idx < 2048; idx += 256) {
        int jj = idx >> 5, c4 = idx & 31;
        float4 v0 = ((const float4*)z)[((size_t)i0       * Nn + j0 + jj) * 32 + c4];
        float4 v1 = ((const float4*)z)[((size_t)(i0 + 1) * Nn + j0 + jj) * 32 + c4];
        int sp = jj * 32 + (c4 ^ (jj & 31));
        ((float4*)sz0)[sp] = v0;
        ((float4*)sz1)[sp] = v1;
    }
    __syncthreads();

    unsigned long long a0[12] = {}, a1[12] = {};
    const int sw = jl & 31;
    const float* zr0 = sz0 + jl * 128;
    const float* zr1 = sz1 + jl * 128;
    #pragma unroll
    for (int cc = 0; cc < 8; cc++) {
        int c4 = g * 8 + cc;
        ulonglong2 zz0 = *(const ulonglong2*)(zr0 + ((c4 ^ sw) << 2));
        ulonglong2 zz1 = *(const ulonglong2*)(zr1 + ((c4 ^ sw) << 2));
        #pragma unroll
        for (int h = 0; h < 12; h++) {
            ulonglong2 ww = *(const ulonglong2*)(swb + h * 128 + (c4 << 2));
            ffma2(a0[h], zz0.x, ww.x);
            ffma2(a0[h], zz0.y, ww.y);
            ffma2(a1[h], zz1.x, ww.x);
            ffma2(a1[h], zz1.y, ww.y);
        }
    }
    #pragma unroll
    for (int h = 0; h < 12; h++) {
        F2U u; u.u = a0[h]; part[(g * 12 + h) * 64 + jl]        = u.f.x + u.f.y;
        F2U v; v.u = a1[h]; part[3072 + (g * 12 + h) * 64 + jl] = v.f.x + v.f.y;
    }
    __syncthreads();

    if (t < 128) {
        int ii = t >> 6, tl = t & 63;
        const float* p = part + ii * 3072;
        #pragma unroll
        for (int h = 0; h < 12; h++) {
            float s = p[h * 64 + tl] + p[(12 + h) * 64 + tl]
                    + p[(24 + h) * 64 + tl] + p[(36 + h) * 64 + tl];
            g_bias[((size_t)h * Nn + i0 + ii) * Nn + j0 + tl] =
                0.5773502691896258f * (s + sbb[h]);
        }
    }
}

// ---------------- KB: fused logits + softmax; warp = h, 2 i's per CTA ----------
// smem: 12 warps x 2 rows x 768 floats = 73728 B; no cross-warp sync needed.
#define SMB_BYTES (12 * 2 * 768 * 4)
__global__ __launch_bounds__(384) void attn_logits2(const float* __restrict__ mask,
                                                    const float* __restrict__ hwraw) {
    extern __shared__ float srows[];
    int i0 = blockIdx.x * 2;
    int h = threadIdx.x >> 5, lane = threadIdx.x & 31;
    float* row0 = srows + (h * 2 + 0) * 768;
    float* row1 = srows + (h * 2 + 1) * 768;

    float q[2][16], qp[2][12];
    #pragma unroll
    for (int ii = 0; ii < 2; ii++) {
        const float4* qs = (const float4*)(g_proj + (size_t)(i0+ii) * NPROJ + h * 16);
        #pragma unroll
        for (int c = 0; c < 4; c++) {
            float4 v = qs[c];
            q[ii][c*4+0] = v.x; q[ii][c*4+1] = v.y; q[ii][c*4+2] = v.z; q[ii][c*4+3] = v.w;
        }
        const float4* ps = (const float4*)(g_qpts + (size_t)(i0+ii) * 144 + h * 12);
        #pragma unroll
        for (int c = 0; c < 3; c++) {
            float4 v = ps[c];
            qp[ii][c*4+0] = v.x; qp[ii][c*4+1] = v.y; qp[ii][c*4+2] = v.z; qp[ii][c*4+3] = v.w;
        }
    }
    float x = hwraw[h];
    float hwv = ((x > 20.f) ? x : log1pf(expf(x))) * 0.13608276348795434f;
    float mi0 = mask[i0], mi1 = mask[i0 + 1];
    const float s1 = 0.14433756729740643f;
    float mx0 = -3.4e38f, mx1 = -3.4e38f;

    for (int j0 = 0; j0 < Nn; j0 += 32) {
        int j = j0 + lane;
        float mj = mask[j];
        const float4* kb = (const float4*)(g_kh + ((size_t)h * Nn + j) * 16);
        float4 k0 = kb[0], k1 = kb[1], k2 = kb[2], k3 = kb[3];
        const float4* pb = (const float4*)(g_kph + ((size_t)h * Nn + j) * 12);
        float4 p0 = pb[0], p1 = pb[1], p2 = pb[2];

        #pragma unroll
        for (int ii = 0; ii < 2; ii++) {
            float qk = 0.f;
            qk = fmaf(q[ii][0],  k0.x, qk); qk = fmaf(q[ii][1],  k0.y, qk);
            qk = fmaf(q[ii][2],  k0.z, qk); qk = fmaf(q[ii][3],  k0.w, qk);
            qk = fmaf(q[ii][4],  k1.x, qk); qk = fmaf(q[ii][5],  k1.y, qk);
            qk = fmaf(q[ii][6],  k1.z, qk); qk = fmaf(q[ii][7],  k1.w, qk);
            qk = fmaf(q[ii][8],  k2.x, qk); qk = fmaf(q[ii][9],  k2.y, qk);
            qk = fmaf(q[ii][10], k2.z, qk); qk = fmaf(q[ii][11], k2.w, qk);
            qk = fmaf(q[ii][12], k3.x, qk); qk = fmaf(q[ii][13], k3.y, qk);
            qk = fmaf(q[ii][14], k3.z, qk); qk = fmaf(q[ii][15], k3.w, qk);

            float d2 = 0.f, d;
            d = qp[ii][0]  - p0.x; d2 = fmaf(d, d, d2);
            d = qp[ii][1]  - p0.y; d2 = fmaf(d, d, d2);
            d = qp[ii][2]  - p0.z; d2 = fmaf(d, d, d2);
            d = qp[ii][3]  - p0.w; d2 = fmaf(d, d, d2);
            d = qp[ii][4]  - p1.x; d2 = fmaf(d, d, d2);
            d = qp[ii][5]  - p1.y; d2 = fmaf(d, d, d2);
            d = qp[ii][6]  - p1.z; d2 = fmaf(d, d, d2);
            d = qp[ii][7]  - p1.w; d2 = fmaf(d, d, d2);
            d = qp[ii][8]  - p2.x; d2 = fmaf(d, d, d2);
            d = qp[ii][9]  - p2.y; d2 = fmaf(d, d, d2);
            d = qp[ii][10] - p2.z; d2 = fmaf(d, d, d2);
            d = qp[ii][11] - p2.w; d2 = fmaf(d, d, d2);

            float bias = g_bias[((size_t)h * Nn + i0 + ii) * Nn + j];
            float mi = ii ? mi1 : mi0;
            float lg = qk * s1 + bias - 0.5f * hwv * d2 + INFV * (mi * mj - 1.f);
            if (ii == 0) { row0[j] = lg; mx0 = fmaxf(mx0, lg); }
            else         { row1[j] = lg; mx1 = fmaxf(mx1, lg); }
        }
    }

    #pragma unroll
    for (int off = 16; off; off >>= 1) {
        mx0 = fmaxf(mx0, __shfl_xor_sync(0xffffffffu, mx0, off));
        mx1 = fmaxf(mx1, __shfl_xor_sync(0xffffffffu, mx1, off));
    }
    float s0 = 0.f, sum1 = 0.f;
    for (int jj = lane; jj < Nn; jj += 32) {
        float e0 = __expf(row0[jj] - mx0); row0[jj] = e0; s0   += e0;
        float e1 = __expf(row1[jj] - mx1); row1[jj] = e1; sum1 += e1;
    }
    #pragma unroll
    for (int off = 16; off; off >>= 1) {
        s0   += __shfl_xor_sync(0xffffffffu, s0,   off);
        sum1 += __shfl_xor_sync(0xffffffffu, sum1, off);
    }
    float inv0 = 1.0f / s0, inv1 = 1.0f / sum1;
    float* a0 = g_a + ((size_t)h * Nn + i0) * Nn;
    float* a1 = a0 + Nn;
    for (int jj = lane; jj < Nn; jj += 32) {
        a0[jj] = row0[jj] * inv0;
        a1[jj] = row1[jj] * inv1;
    }
}

// ---------------- KC: o_pair, channel-split: grid (2 chalf, 768 i), 128 thr ------
__global__ __launch_bounds__(128) void opair(const float* __restrict__ z) {
    __shared__ float sz[32 * 64];
    __shared__ float sa[12 * 32];
    int chalf = blockIdx.x, i = blockIdx.y;
    int t = threadIdx.x, w = t >> 5, lane = t & 31;

    unsigned long long acc[3] = {};

    for (int j0 = 0; j0 < Nn; j0 += 32) {
        __syncthreads();
        for (int idx = t; idx < 512; idx += 128) {
            int jj = idx >> 4, c4 = idx & 15;
            ((float4*)sz)[jj * 16 + c4] =
                ((const float4*)z)[((size_t)i * Nn + j0 + jj) * 32 + chalf * 16 + c4];
        }
        if (t < 96) {
            int hh = t >> 3, c = t & 7;
            ((float4*)sa)[t] =
                *((const float4*)(g_a + ((size_t)hh * Nn + i) * Nn + j0) + c);
        }
        __syncthreads();

        #pragma unroll
        for (int jj4 = 0; jj4 < 8; jj4++) {
            float4 a0 = ((const float4*)(sa + (w * 3 + 0) * 32))[jj4];
            float4 a1 = ((const float4*)(sa + (w * 3 + 1) * 32))[jj4];
            float4 a2 = ((const float4*)(sa + (w * 3 + 2) * 32))[jj4];
            float a0v[4] = {a0.x, a0.y, a0.z, a0.w};
            float a1v[4] = {a1.x, a1.y, a1.z, a1.w};
            float a2v[4] = {a2.x, a2.y, a2.z, a2.w};
            #pragma unroll
            for (int sub = 0; sub < 4; sub++) {
                int jj = jj4 * 4 + sub;
                unsigned long long zz =
                    *(const unsigned long long*)(sz + jj * 64 + lane * 2);
                F2U u0, u1, u2;
                u0.f.x = a0v[sub]; u0.f.y = a0v[sub];
                u1.f.x = a1v[sub]; u1.f.y = a1v[sub];
                u2.f.x = a2v[sub]; u2.f.y = a2v[sub];
                ffma2(acc[0], u0.u, zz);
                ffma2(acc[1], u1.u, zz);
                ffma2(acc[2], u2.u, zz);
            }
        }
    }

    float* crow = g_cat + (size_t)i * DOUT + 576 + chalf * 64;
    #pragma unroll
    for (int e = 0; e < 3; e++) {
        F2U u; u.u = acc[e];
        *(float2*)(crow + (w * 3 + e) * 128 + lane * 2) = u.f;
    }
}

// ---------------- KD: o + o_pt + inverse frame + norms; 2 i's per CTA ----------
__global__ __launch_bounds__(384) void attn_out(const float* __restrict__ rot,
                                                const float* __restrict__ trans) {
    int i0 = blockIdx.x * 2;
    int h = threadIdx.x >> 5, lane = threadIdx.x & 31;

    float ao[2][16] = {};
    float ap[2][24] = {};

    for (int j0 = 0; j0 < Nn; j0 += 32) {
        int j = j0 + lane;
        const float4* vb = (const float4*)(g_vh + ((size_t)h * Nn + j) * 16);
        float4 v0 = vb[0], v1 = vb[1], v2 = vb[2], v3 = vb[3];
        const float4* pb = (const float4*)(g_vph + ((size_t)h * Nn + j) * 24);
        float4 p0 = pb[0], p1 = pb[1], p2 = pb[2], p3 = pb[3], p4 = pb[4], p5 = pb[5];

        #pragma unroll
        for (int ii = 0; ii < 2; ii++) {
            float a = g_a[((size_t)h * Nn + i0 + ii) * Nn + j];
            ao[ii][0]  = fmaf(a, v0.x, ao[ii][0]);  ao[ii][1]  = fmaf(a, v0.y, ao[ii][1]);
            ao[ii][2]  = fmaf(a, v0.z, ao[ii][2]);  ao[ii][3]  = fmaf(a, v0.w, ao[ii][3]);
            ao[ii][4]  = fmaf(a, v1.x, ao[ii][4]);  ao[ii][5]  = fmaf(a, v1.y, ao[ii][5]);
            ao[ii][6]  = fmaf(a, v1.z, ao[ii][6]);  ao[ii][7]  = fmaf(a, v1.w, ao[ii][7]);
            ao[ii][8]  = fmaf(a, v2.x, ao[ii][8]);  ao[ii][9]  = fmaf(a, v2.y, ao[ii][9]);
            ao[ii][10] = fmaf(a, v2.z, ao[ii][10]); ao[ii][11] = fmaf(a, v2.w, ao[ii][11]);
            ao[ii][12] = fmaf(a, v3.x, ao[ii][12]); ao[ii][13] = fmaf(a, v3.y, ao[ii][13]);
            ao[ii][14] = fmaf(a, v3.z, ao[ii][14]); ao[ii][15] = fmaf(a, v3.w, ao[ii][15]);

            ap[ii][0]  = fmaf(a, p0.x, ap[ii][0]);  ap[ii][1]  = fmaf(a, p0.y, ap[ii][1]);
            ap[ii][2]  = fmaf(a, p0.z, ap[ii][2]);  ap[ii][3]  = fmaf(a, p0.w, ap[ii][3]);
            ap[ii][4]  = fmaf(a, p1.x, ap[ii][4]);  ap[ii][5]  = fmaf(a, p1.y, ap[ii][5]);
            ap[ii][6]  = fmaf(a, p1.z, ap[ii][6]);  ap[ii][7]  = fmaf(a, p1.w, ap[ii][7]);
            ap[ii][8]  = fmaf(a, p2.x, ap[ii][8]);  ap[ii][9]  = fmaf(a, p2.y, ap[ii][9]);
            ap[ii][10] = fmaf(a, p2.z, ap[ii][10]); ap[ii][11] = fmaf(a, p2.w, ap[ii][11]);
            ap[ii][12] = fmaf(a, p3.x, ap[ii][12]); ap[ii][13] = fmaf(a, p3.y, ap[ii][13]);
            ap[ii][14] = fmaf(a, p3.z, ap[ii][14]); ap[ii][15] = fmaf(a, p3.w, ap[ii][15]);
            ap[ii][16] = fmaf(a, p4.x, ap[ii][16]); ap[ii][17] = fmaf(a, p4.y, ap[ii][17]);
            ap[ii][18] = fmaf(a, p4.z, ap[ii][18]); ap[ii][19] = fmaf(a, p4.w, ap[ii][19]);
            ap[ii][20] = fmaf(a, p5.x, ap[ii][20]); ap[ii][21] = fmaf(a, p5.y, ap[ii][21]);
            ap[ii][22] = fmaf(a, p5.z, ap[ii][22]); ap[ii][23] = fmaf(a, p5.w, ap[ii][23]);
        }
    }

    #pragma unroll
    for (int off = 16; off; off >>= 1) {
        #pragma unroll
        for (int ii = 0; ii < 2; ii++) {
            #pragma unroll
            for (int c = 0; c < 16; c++) ao[ii][c] += __shfl_xor_sync(0xffffffffu, ao[ii][c], off);
            #pragma unroll
            for (int e = 0; e < 24; e++) ap[ii][e] += __shfl_xor_sync(0xffffffffu, ap[ii][e], off);
        }
    }

    if (lane == 0) {
        #pragma unroll
        for (int ii = 0; ii < 2; ii++) {
            int i = i0 + ii;
            float* crow = g_cat + (size_t)i * DOUT;
            #pragma unroll
            for (int c = 0; c < 16; c++) crow[h * 16 + c] = ao[ii][c];
            float R[9];
            #pragma unroll
            for (int e = 0; e < 9; e++) R[e] = rot[i * 9 + e];
            float t0 = trans[i*3+0], t1 = trans[i*3+1], t2 = trans[i*3+2];
            #pragma unroll
            for (int p = 0; p < 8; p++) {
                float dx = ap[ii][p*3+0] - t0;
                float dy = ap[ii][p*3+1] - t1;
                float dz = ap[ii][p*3+2] - t2;
                float lx = R[0]*dx + R[3]*dy + R[6]*dz;
                float ly = R[1]*dx + R[4]*dy + R[7]*dz;
                float lz = R[2]*dx + R[5]*dy + R[8]*dz;
                crow[192 + (h*8+p)*3 + 0] = lx;
                crow[192 + (h*8+p)*3 + 1] = ly;
                crow[192 + (h*8+p)*3 + 2] = lz;
                crow[480 + h*8 + p] = sqrtf(lx*lx + ly*ly + lz*lz + 1e-8f);
            }
        }
    }
}

// ---------------- host ----------------
extern "C" void kernel_launch(void* const* d_in, const int* in_sizes, int n_in,
                              void* d_out, int out_size) {
    const float* s      = (const float*)d_in[0];
    const float* z      = (const float*)d_in[1];
    const float* rot    = (const float*)d_in[2];
    const float* trans  = (const float*)d_in[3];
    const float* mask   = (const float*)d_in[4];
    const float* w_q    = (const float*)d_in[5];
    const float* b_q    = (const float*)d_in[6];
    const float* w_kv   = (const float*)d_in[7];
    const float* b_kv   = (const float*)d_in[8];
    const float* w_qp   = (const float*)d_in[9];
    const float* b_qp   = (const float*)d_in[10];
    const float* w_kvp  = (const float*)d_in[11];
    const float* b_kvp  = (const float*)d_in[12];
    const float* w_b    = (const float*)d_in[13];
    const float* b_b    = (const float*)d_in[14];
    const float* hw     = (const float*)d_in[15];
    const float* w_out  = (const float*)d_in[16];
    const float* b_out  = (const float*)d_in[17];
    float* out = (float*)d_out;

    cudaFuncSetAttribute(bias_gemm,    cudaFuncAttributeMaxDynamicSharedMemorySize, SMA_BYTES);
    cudaFuncSetAttribute(attn_logits2, cudaFuncAttributeMaxDynamicSharedMemorySize, SMB_BYTES);

    copy_weights<<<(NPROJ * CSd + 255) / 256, 256>>>(w_q, b_q, w_kv, b_kv,
                                                     w_qp, b_qp, w_kvp, b_kvp);
    gemm_proj<<<dim3(NPROJ / 64, Nn / 64), 256>>>(s);
    prep_pts<<<Nn, 128>>>(rot, trans);
    bias_gemm<<<dim3(12, Nn / 2), 256, SMA_BYTES>>>(z, w_b, b_b);
    attn_logits2<<<Nn / 2, 384, SMB_BYTES>>>(mask, hw);
    opair<<<dim3(2, Nn), 128>>>(z);
    attn_out<<<Nn / 2, 384>>>(rot, trans);
    gemm_out_split<<<dim3(CSd / 64, Nn / 64, 3), 256>>>(w_out);
    gemm_out_combine<<<(Nn * CSd + 255) / 256, 256>>>(b_out, out);
}

// round 12
// speedup vs baseline: 3.9684x; 1.1510x over previous
#include <cuda_runtime.h>
#include <cstdint>
#include <cmath>

#define Nn    768
#define CSd   384
#define NPROJ 1152
#define DOUT  2112
#define INFV  100000.0f

__device__ float g_proj [Nn * NPROJ];
__device__ float g_wcat [NPROJ * CSd];
__device__ float g_bcat [NPROJ];
__device__ float g_kh  [12 * Nn * 16];
__device__ float g_vh  [12 * Nn * 16];
__device__ float g_kph [12 * Nn * 12];
__device__ float g_vph [12 * Nn * 24];
__device__ float g_qpts[Nn * 144];
__device__ float g_bias[(size_t)12 * Nn * Nn];
__device__ float g_a   [(size_t)12 * Nn * Nn];
__device__ float g_cat [Nn * DOUT];
__device__ float g_part[3 * Nn * CSd];

__device__ __forceinline__ void ffma2(unsigned long long& d,
                                      unsigned long long a,
                                      unsigned long long b) {
    asm("fma.rn.f32x2 %0, %1, %2, %0;" : "+l"(d) : "l"(a), "l"(b));
}
union F2U { unsigned long long u; float2 f; };

__device__ __forceinline__ uint32_t smaddr(const void* p) {
    return (uint32_t)__cvta_generic_to_shared(p);
}
__device__ __forceinline__ void cp16(uint32_t dst, const void* src) {
    asm volatile("cp.async.cg.shared.global [%0], [%1], 16;" :: "r"(dst), "l"(src));
}
__device__ __forceinline__ void cp_commit() {
    asm volatile("cp.async.commit_group;");
}
template<int N> __device__ __forceinline__ void cp_wait() {
    asm volatile("cp.async.wait_group %0;" :: "n"(N));
}

// ---------------- K0a: concat projection weights ----------------
__global__ void copy_weights(const float* __restrict__ wq,  const float* __restrict__ bq,
                             const float* __restrict__ wkv, const float* __restrict__ bkv,
                             const float* __restrict__ wqp, const float* __restrict__ bqp,
                             const float* __restrict__ wkvp,const float* __restrict__ bkvp) {
    int idx = blockIdx.x * 256 + threadIdx.x;
    if (idx < NPROJ * CSd) {
        int r = idx / CSd, k = idx - r * CSd;
        float v;
        if      (r < 192) v = wq  [ r        * CSd + k];
        else if (r < 576) v = wkv [(r - 192) * CSd + k];
        else if (r < 720) v = wqp [(r - 576) * CSd + k];
        else              v = wkvp[(r - 720) * CSd + k];
        g_wcat[idx] = v;
    }
    if (idx < NPROJ) {
        int r = idx;
        g_bcat[r] = (r < 192) ? bq[r] : (r < 576) ? bkv[r-192]
                  : (r < 720) ? bqp[r-576] : bkvp[r-720];
    }
}

// ---------------- projection GEMM ----------------
__global__ void gemm_proj(const float* __restrict__ A) {
    constexpr int KK = CSd;
    constexpr int NC = NPROJ;
    const float* B    = g_wcat;
    const float* bias = g_bcat;
    float*       C    = g_proj;

    __shared__ float As[64][17];
    __shared__ float Bs[64][17];
    int t  = threadIdx.x;
    int m0 = blockIdx.y * 64, n0 = blockIdx.x * 64;
    int lr = t >> 2, lc = (t & 3) * 4;
    int ty = (t >> 4) * 4, tx = (t & 15) * 4;
    float acc[4][4] = {};

    for (int k0 = 0; k0 < KK; k0 += 16) {
        __syncthreads();
        float4 a4 = *(const float4*)(A + (size_t)(m0 + lr) * KK + k0 + lc);
        float4 b4 = *(const float4*)(B + (size_t)(n0 + lr) * KK + k0 + lc);
        As[lr][lc] = a4.x; As[lr][lc+1] = a4.y; As[lr][lc+2] = a4.z; As[lr][lc+3] = a4.w;
        Bs[lr][lc] = b4.x; Bs[lr][lc+1] = b4.y; Bs[lr][lc+2] = b4.z; Bs[lr][lc+3] = b4.w;
        __syncthreads();
        #pragma unroll
        for (int kk = 0; kk < 16; kk++) {
            float av[4], bv[4];
            #pragma unroll
            for (int r = 0; r < 4; r++) av[r] = As[ty + r][kk];
            #pragma unroll
            for (int c = 0; c < 4; c++) bv[c] = Bs[tx + c][kk];
            #pragma unroll
            for (int r = 0; r < 4; r++)
                #pragma unroll
                for (int c = 0; c < 4; c++)
                    acc[r][c] = fmaf(av[r], bv[c], acc[r][c]);
        }
    }
    #pragma unroll
    for (int r = 0; r < 4; r++)
        #pragma unroll
        for (int c = 0; c < 4; c++)
            C[(size_t)(m0 + ty + r) * NC + n0 + tx + c] = acc[r][c] + bias[n0 + tx + c];
}

// ---------------- output GEMM, K split 3 ----------------
__global__ void gemm_out_split(const float* __restrict__ w_out) {
    constexpr int KCH = DOUT / 3;    // 704
    const float* A = g_cat;
    const float* B = w_out;
    int kc = blockIdx.z;
    float* C = g_part + (size_t)kc * Nn * CSd;

    __shared__ float As[64][17];
    __shared__ float Bs[64][17];
    int t  = threadIdx.x;
    int m0 = blockIdx.y * 64, n0 = blockIdx.x * 64;
    int lr = t >> 2, lc = (t & 3) * 4;
    int ty = (t >> 4) * 4, tx = (t & 15) * 4;
    float acc[4][4] = {};

    for (int k0 = kc * KCH; k0 < (kc + 1) * KCH; k0 += 16) {
        __syncthreads();
        float4 a4 = *(const float4*)(A + (size_t)(m0 + lr) * DOUT + k0 + lc);
        float4 b4 = *(const float4*)(B + (size_t)(n0 + lr) * DOUT + k0 + lc);
        As[lr][lc] = a4.x; As[lr][lc+1] = a4.y; As[lr][lc+2] = a4.z; As[lr][lc+3] = a4.w;
        Bs[lr][lc] = b4.x; Bs[lr][lc+1] = b4.y; Bs[lr][lc+2] = b4.z; Bs[lr][lc+3] = b4.w;
        __syncthreads();
        #pragma unroll
        for (int kk = 0; kk < 16; kk++) {
            float av[4], bv[4];
            #pragma unroll
            for (int r = 0; r < 4; r++) av[r] = As[ty + r][kk];
            #pragma unroll
            for (int c = 0; c < 4; c++) bv[c] = Bs[tx + c][kk];
            #pragma unroll
            for (int r = 0; r < 4; r++)
                #pragma unroll
                for (int c = 0; c < 4; c++)
                    acc[r][c] = fmaf(av[r], bv[c], acc[r][c]);
        }
    }
    #pragma unroll
    for (int r = 0; r < 4; r++)
        #pragma unroll
        for (int c = 0; c < 4; c++)
            C[(size_t)(m0 + ty + r) * CSd + n0 + tx + c] = acc[r][c];
}

__global__ void gemm_out_combine(const float* __restrict__ b_out, float* __restrict__ out) {
    int idx = blockIdx.x * 256 + threadIdx.x;
    if (idx < Nn * CSd) {
        int c = idx % CSd;
        out[idx] = g_part[idx] + g_part[idx + Nn * CSd] + g_part[idx + 2 * Nn * CSd]
                 + b_out[c];
    }
}

// ---------------- K0b: rotate points, repack k/v into [h][j][*] ----------------
__global__ void prep_pts(const float* __restrict__ rot, const float* __restrict__ trans) {
    int n = blockIdx.x;
    const float* pr = g_proj + (size_t)n * NPROJ;
    float R[9];
    #pragma unroll
    for (int e = 0; e < 9; e++) R[e] = rot[n * 9 + e];
    float tr[3] = {trans[n*3+0], trans[n*3+1], trans[n*3+2]};

    for (int t = threadIdx.x; t < 960; t += blockDim.x) {
        if (t < 384) {
            int h = t >> 5, c = t & 31;
            float v = pr[192 + h * 32 + c];
            if (c < 16) g_kh[((size_t)h * Nn + n) * 16 + c]        = v;
        else        g_vh[((size_t)h * Nn + n) * 16 + (c - 16)] = v;
        } else if (t < 528) {
            int e = t - 384;
            int g = e / 3, ax = e - g * 3;
            const float* src = pr + 576 + g * 3;
            g_qpts[n * 144 + e] =
                R[ax*3+0]*src[0] + R[ax*3+1]*src[1] + R[ax*3+2]*src[2] + tr[ax];
        } else {
            int e2 = t - 528;
            int g = e2 / 3, ax = e2 - g * 3;
            const float* src = pr + 720 + g * 3;
            float val = R[ax*3+0]*src[0] + R[ax*3+1]*src[1] + R[ax*3+2]*src[2] + tr[ax];
            int h = g / 12, pp = g - h * 12;
            if (pp < 4) g_kph[((size_t)h * Nn + n) * 12 + pp * 3 + ax]       = val;
            else        g_vph[((size_t)h * Nn + n) * 24 + (pp - 4) * 3 + ax] = val;
        }
    }
}

// ---------------- KA: bias GEMM, persistent CTA=i, cp.async double-buffer --------
// smem floats: zb[2][8192] | swb 1536 | sbb 16 | part 3072  = 21008
#define SMA_BYTES (21008 * 4)
__global__ __launch_bounds__(256) void bias_gemm(const float* __restrict__ z,
                                                 const float* __restrict__ w_b,
                                                 const float* __restrict__ b_b) {
    extern __shared__ float sm[];
    float* swb  = sm + 16384;
    float* sbb  = sm + 17920;
    float* part = sm + 17936;

    const int i = blockIdx.x;
    const int t = threadIdx.x;
    const int g = t >> 6, jl = t & 63;

    for (int idx = t; idx < 384; idx += 256)
        ((float4*)swb)[idx] = ((const float4*)w_b)[idx];
    if (t < 12) sbb[t] = b_b[t];

    const float4* zbase = (const float4*)z + (size_t)i * Nn * 32;

    // prologue: tiles 0 and 1
    #pragma unroll
    for (int p = 0; p < 2; p++) {
        float* buf = sm + p * 8192;
        const float4* src = zbase + (size_t)p * 64 * 32;
        #pragma unroll
        for (int k = 0; k < 8; k++) {
            int idx = t + k * 256;
            int jj = idx >> 5, c4 = idx & 31;
            cp16(smaddr(buf + (size_t)(jj * 32 + (c4 ^ (jj & 31))) * 4),
                 src + (size_t)jj * 32 + c4);
        }
        cp_commit();
    }

    for (int tt = 0; tt < 12; tt++) {
        if (tt < 11) cp_wait<1>(); else cp_wait<0>();
        __syncthreads();

        const float* zr = sm + (tt & 1) * 8192 + jl * 128;
        const int sw = jl & 31;
        unsigned long long acc[12] = {};
        #pragma unroll
        for (int cc = 0; cc < 8; cc++) {
            int c4 = g * 8 + cc;
            ulonglong2 zz = *(const ulonglong2*)(zr + ((c4 ^ sw) << 2));
            #pragma unroll
            for (int h = 0; h < 12; h++) {
                ulonglong2 ww = *(const ulonglong2*)(swb + h * 128 + (c4 << 2));
                ffma2(acc[h], zz.x, ww.x);
                ffma2(acc[h], zz.y, ww.y);
            }
        }
        #pragma unroll
        for (int h = 0; h < 12; h++) {
            F2U u; u.u = acc[h];
            part[(g * 12 + h) * 64 + jl] = u.f.x + u.f.y;
        }
        __syncthreads();   // parts complete; all threads done reading zb[tt&1]

        if (t < 64) {
            #pragma unroll
            for (int h = 0; h < 12; h++) {
                float s2 = part[h * 64 + t] + part[(12 + h) * 64 + t]
                         + part[(24 + h) * 64 + t] + part[(36 + h) * 64 + t];
                g_bias[((size_t)h * Nn + i) * Nn + tt * 64 + t] =
                    0.5773502691896258f * (s2 + sbb[h]);
            }
        }
        if (tt + 2 < 12) {
            float* buf = sm + (tt & 1) * 8192;
            const float4* src = zbase + (size_t)(tt + 2) * 64 * 32;
            #pragma unroll
            for (int k = 0; k < 8; k++) {
                int idx = t + k * 256;
                int jj = idx >> 5, c4 = idx & 31;
                cp16(smaddr(buf + (size_t)(jj * 32 + (c4 ^ (jj & 31))) * 4),
                     src + (size_t)jj * 32 + c4);
            }
            cp_commit();
        }
    }
}

// ---------------- KB: fused logits + softmax; warp = h, 2 i's per CTA ----------
#define SMB_BYTES (12 * 2 * 768 * 4)
__global__ __launch_bounds__(384) void attn_logits2(const float* __restrict__ mask,
                                                    const float* __restrict__ hwraw) {
    extern __shared__ float srows[];
    int i0 = blockIdx.x * 2;
    int h = threadIdx.x >> 5, lane = threadIdx.x & 31;
    float* row0 = srows + (h * 2 + 0) * 768;
    float* row1 = srows + (h * 2 + 1) * 768;

    float q[2][16], qp[2][12];
    #pragma unroll
    for (int ii = 0; ii < 2; ii++) {
        const float4* qs = (const float4*)(g_proj + (size_t)(i0+ii) * NPROJ + h * 16);
        #pragma unroll
        for (int c = 0; c < 4; c++) {
            float4 v = qs[c];
            q[ii][c*4+0] = v.x; q[ii][c*4+1] = v.y; q[ii][c*4+2] = v.z; q[ii][c*4+3] = v.w;
        }
        const float4* ps = (const float4*)(g_qpts + (size_t)(i0+ii) * 144 + h * 12);
        #pragma unroll
        for (int c = 0; c < 3; c++) {
            float4 v = ps[c];
            qp[ii][c*4+0] = v.x; qp[ii][c*4+1] = v.y; qp[ii][c*4+2] = v.z; qp[ii][c*4+3] = v.w;
        }
    }
    float x = hwraw[h];
    float hwv = ((x > 20.f) ? x : log1pf(expf(x))) * 0.13608276348795434f;
    float mi0 = mask[i0], mi1 = mask[i0 + 1];
    const float s1 = 0.14433756729740643f;
    float mx0 = -3.4e38f, mx1 = -3.4e38f;

    for (int j0 = 0; j0 < Nn; j0 += 32) {
        int j = j0 + lane;
        float mj = mask[j];
        const float4* kb = (const float4*)(g_kh + ((size_t)h * Nn + j) * 16);
        float4 k0 = kb[0], k1 = kb[1], k2 = kb[2], k3 = kb[3];
        const float4* pb = (const float4*)(g_kph + ((size_t)h * Nn + j) * 12);
        float4 p0 = pb[0], p1 = pb[1], p2 = pb[2];

        #pragma unroll
        for (int ii = 0; ii < 2; ii++) {
            float qk = 0.f;
            qk = fmaf(q[ii][0],  k0.x, qk); qk = fmaf(q[ii][1],  k0.y, qk);
            qk = fmaf(q[ii][2],  k0.z, qk); qk = fmaf(q[ii][3],  k0.w, qk);
            qk = fmaf(q[ii][4],  k1.x, qk); qk = fmaf(q[ii][5],  k1.y, qk);
            qk = fmaf(q[ii][6],  k1.z, qk); qk = fmaf(q[ii][7],  k1.w, qk);
            qk = fmaf(q[ii][8],  k2.x, qk); qk = fmaf(q[ii][9],  k2.y, qk);
            qk = fmaf(q[ii][10], k2.z, qk); qk = fmaf(q[ii][11], k2.w, qk);
            qk = fmaf(q[ii][12], k3.x, qk); qk = fmaf(q[ii][13], k3.y, qk);
            qk = fmaf(q[ii][14], k3.z, qk); qk = fmaf(q[ii][15], k3.w, qk);

            float d2 = 0.f, d;
            d = qp[ii][0]  - p0.x; d2 = fmaf(d, d, d2);
            d = qp[ii][1]  - p0.y; d2 = fmaf(d, d, d2);
            d = qp[ii][2]  - p0.z; d2 = fmaf(d, d, d2);
            d = qp[ii][3]  - p0.w; d2 = fmaf(d, d, d2);
            d = qp[ii][4]  - p1.x; d2 = fmaf(d, d, d2);
            d = qp[ii][5]  - p1.y; d2 = fmaf(d, d, d2);
            d = qp[ii][6]  - p1.z; d2 = fmaf(d, d, d2);
            d = qp[ii][7]  - p1.w; d2 = fmaf(d, d, d2);
            d = qp[ii][8]  - p2.x; d2 = fmaf(d, d, d2);
            d = qp[ii][9]  - p2.y; d2 = fmaf(d, d, d2);
            d = qp[ii][10] - p2.z; d2 = fmaf(d, d, d2);
            d = qp[ii][11] - p2.w; d2 = fmaf(d, d, d2);

            float bias = g_bias[((size_t)h * Nn + i0 + ii) * Nn + j];
            float mi = ii ? mi1 : mi0;
            float lg = qk * s1 + bias - 0.5f * hwv * d2 + INFV * (mi * mj - 1.f);
            if (ii == 0) { row0[j] = lg; mx0 = fmaxf(mx0, lg); }
            else         { row1[j] = lg; mx1 = fmaxf(mx1, lg); }
        }
    }

    #pragma unroll
    for (int off = 16; off; off >>= 1) {
        mx0 = fmaxf(mx0, __shfl_xor_sync(0xffffffffu, mx0, off));
        mx1 = fmaxf(mx1, __shfl_xor_sync(0xffffffffu, mx1, off));
    }
    float s0 = 0.f, sum1 = 0.f;
    for (int jj = lane; jj < Nn; jj += 32) {
        float e0 = __expf(row0[jj] - mx0); row0[jj] = e0; s0   += e0;
        float e1 = __expf(row1[jj] - mx1); row1[jj] = e1; sum1 += e1;
    }
    #pragma unroll
    for (int off = 16; off; off >>= 1) {
        s0   += __shfl_xor_sync(0xffffffffu, s0,   off);
        sum1 += __shfl_xor_sync(0xffffffffu, sum1, off);
    }
    float inv0 = 1.0f / s0, inv1 = 1.0f / sum1;
    float* a0 = g_a + ((size_t)h * Nn + i0) * Nn;
    float* a1 = a0 + Nn;
    for (int jj = lane; jj < Nn; jj += 32) {
        a0[jj] = row0[jj] * inv0;
        a1[jj] = row1[jj] * inv1;
    }
}

// ---------------- KC: o_pair, channel-split + cp.async double-buffer ------------
// smem floats: zb[2][2048] | sab[2][384]  = 4864
#define SMC_BYTES (4864 * 4)
__global__ __launch_bounds__(128) void opair(const float* __restrict__ z) {
    extern __shared__ float smc[];
    float* zb  = smc;          // [2][2048]
    float* sab = smc + 4096;   // [2][384]
    const int chalf = blockIdx.x, i = blockIdx.y;
    const int t = threadIdx.x, w = t >> 5, lane = t & 31;

    unsigned long long acc[3] = {};

    // prologue: tiles 0 and 1
    #pragma unroll
    for (int p = 0; p < 2; p++) {
        float* zdst = zb + p * 2048;
        float* adst = sab + p * 384;
        const float4* zsrc = (const float4*)z + ((size_t)i * Nn + p * 32) * 32 + chalf * 16;
        #pragma unroll
        for (int k = 0; k < 4; k++) {
            int idx = t + k * 128;
            int jj = idx >> 4, c4 = idx & 15;
            cp16(smaddr(zdst + (size_t)(jj * 16 + c4) * 4), zsrc + (size_t)jj * 32 + c4);
        }
        if (t < 96) {
            int hh = t >> 3, c = t & 7;
            cp16(smaddr(adst + (size_t)(hh * 8 + c) * 4),
                 (const float4*)(g_a + ((size_t)hh * Nn + i) * Nn + p * 32) + c);
        }
        cp_commit();
    }

    for (int tt = 0; tt < 24; tt++) {
        if (tt < 23) cp_wait<1>(); else cp_wait<0>();
        __syncthreads();

        const float* sz = zb + (tt & 1) * 2048;
        const float* sa = sab + (tt & 1) * 384;

        #pragma unroll
        for (int jj4 = 0; jj4 < 8; jj4++) {
            float4 a0 = ((const float4*)(sa + (w * 3 + 0) * 32))[jj4];
            float4 a1 = ((const float4*)(sa + (w * 3 + 1) * 32))[jj4];
            float4 a2 = ((const float4*)(sa + (w * 3 + 2) * 32))[jj4];
            float a0v[4] = {a0.x, a0.y, a0.z, a0.w};
            float a1v[4] = {a1.x, a1.y, a1.z, a1.w};
            float a2v[4] = {a2.x, a2.y, a2.z, a2.w};
            #pragma unroll
            for (int sub = 0; sub < 4; sub++) {
                int jj = jj4 * 4 + sub;
                unsigned long long zz =
                    *(const unsigned long long*)(sz + jj * 64 + lane * 2);
                F2U u0, u1, u2;
                u0.f.x = a0v[sub]; u0.f.y = a0v[sub];
                u1.f.x = a1v[sub]; u1.f.y = a1v[sub];
                u2.f.x = a2v[sub]; u2.f.y = a2v[sub];
                ffma2(acc[0], u0.u, zz);
                ffma2(acc[1], u1.u, zz);
                ffma2(acc[2], u2.u, zz);
            }
        }
        __syncthreads();   // all threads done reading buffers for tile tt

        if (tt + 2 < 24) {
            float* zdst = zb + (tt & 1) * 2048;
            float* adst = sab + (tt & 1) * 384;
            const float4* zsrc = (const float4*)z
                + ((size_t)i * Nn + (tt + 2) * 32) * 32 + chalf * 16;
            #pragma unroll
            for (int k = 0; k < 4; k++) {
                int idx = t + k * 128;
                int jj = idx >> 4, c4 = idx & 15;
                cp16(smaddr(zdst + (size_t)(jj * 16 + c4) * 4), zsrc + (size_t)jj * 32 + c4);
            }
            if (t < 96) {
                int hh = t >> 3, c = t & 7;
                cp16(smaddr(adst + (size_t)(hh * 8 + c) * 4),
                     (const float4*)(g_a + ((size_t)hh * Nn + i) * Nn + (tt + 2) * 32) + c);
            }
            cp_commit();
        }
    }

    float* crow = g_cat + (size_t)i * DOUT + 576 + chalf * 64;
    #pragma unroll
    for (int e = 0; e < 3; e++) {
        F2U u; u.u = acc[e];
        *(float2*)(crow + (w * 3 + e) * 128 + lane * 2) = u.f;
    }
}

// ---------------- KD: o + o_pt + inverse frame + norms; 2 i's per CTA ----------
__global__ __launch_bounds__(384) void attn_out(const float* __restrict__ rot,
                                                const float* __restrict__ trans) {
    int i0 = blockIdx.x * 2;
    int h = threadIdx.x >> 5, lane = threadIdx.x & 31;

    float ao[2][16] = {};
    float ap[2][24] = {};

    for (int j0 = 0; j0 < Nn; j0 += 32) {
        int j = j0 + lane;
        const float4* vb = (const float4*)(g_vh + ((size_t)h * Nn + j) * 16);
        float4 v0 = vb[0], v1 = vb[1], v2 = vb[2], v3 = vb[3];
        const float4* pb = (const float4*)(g_vph + ((size_t)h * Nn + j) * 24);
        float4 p0 = pb[0], p1 = pb[1], p2 = pb[2], p3 = pb[3], p4 = pb[4], p5 = pb[5];

        #pragma unroll
        for (int ii = 0; ii < 2; ii++) {
            float a = g_a[((size_t)h * Nn + i0 + ii) * Nn + j];
            ao[ii][0]  = fmaf(a, v0.x, ao[ii][0]);  ao[ii][1]  = fmaf(a, v0.y, ao[ii][1]);
            ao[ii][2]  = fmaf(a, v0.z, ao[ii][2]);  ao[ii][3]  = fmaf(a, v0.w, ao[ii][3]);
            ao[ii][4]  = fmaf(a, v1.x, ao[ii][4]);  ao[ii][5]  = fmaf(a, v1.y, ao[ii][5]);
            ao[ii][6]  = fmaf(a, v1.z, ao[ii][6]);  ao[ii][7]  = fmaf(a, v1.w, ao[ii][7]);
            ao[ii][8]  = fmaf(a, v2.x, ao[ii][8]);  ao[ii][9]  = fmaf(a, v2.y, ao[ii][9]);
            ao[ii][10] = fmaf(a, v2.z, ao[ii][10]); ao[ii][11] = fmaf(a, v2.w, ao[ii][11]);
            ao[ii][12] = fmaf(a, v3.x, ao[ii][12]); ao[ii][13] = fmaf(a, v3.y, ao[ii][13]);
            ao[ii][14] = fmaf(a, v3.z, ao[ii][14]); ao[ii][15] = fmaf(a, v3.w, ao[ii][15]);

            ap[ii][0]  = fmaf(a, p0.x, ap[ii][0]);  ap[ii][1]  = fmaf(a, p0.y, ap[ii][1]);
            ap[ii][2]  = fmaf(a, p0.z, ap[ii][2]);  ap[ii][3]  = fmaf(a, p0.w, ap[ii][3]);
            ap[ii][4]  = fmaf(a, p1.x, ap[ii][4]);  ap[ii][5]  = fmaf(a, p1.y, ap[ii][5]);
            ap[ii][6]  = fmaf(a, p1.z, ap[ii][6]);  ap[ii][7]  = fmaf(a, p1.w, ap[ii][7]);
            ap[ii][8]  = fmaf(a, p2.x, ap[ii][8]);  ap[ii][9]  = fmaf(a, p2.y, ap[ii][9]);
            ap[ii][10] = fmaf(a, p2.z, ap[ii][10]); ap[ii][11] = fmaf(a, p2.w, ap[ii][11]);
            ap[ii][12] = fmaf(a, p3.x, ap[ii][12]); ap[ii][13] = fmaf(a, p3.y, ap[ii][13]);
            ap[ii][14] = fmaf(a, p3.z, ap[ii][14]); ap[ii][15] = fmaf(a, p3.w, ap[ii][15]);
            ap[ii][16] = fmaf(a, p4.x, ap[ii][16]); ap[ii][17] = fmaf(a, p4.y, ap[ii][17]);
            ap[ii][18] = fmaf(a, p4.z, ap[ii][18]); ap[ii][19] = fmaf(a, p4.w, ap[ii][19]);
            ap[ii][20] = fmaf(a, p5.x, ap[ii][20]); ap[ii][21] = fmaf(a, p5.y, ap[ii][21]);
            ap[ii][22] = fmaf(a, p5.z, ap[ii][22]); ap[ii][23] = fmaf(a, p5.w, ap[ii][23]);
        }
    }

    #pragma unroll
    for (int off = 16; off; off >>= 1) {
        #pragma unroll
        for (int ii = 0; ii < 2; ii++) {
            #pragma unroll
            for (int c = 0; c < 16; c++) ao[ii][c] += __shfl_xor_sync(0xffffffffu, ao[ii][c], off);
            #pragma unroll
            for (int e = 0; e < 24; e++) ap[ii][e] += __shfl_xor_sync(0xffffffffu, ap[ii][e], off);
        }
    }

    if (lane == 0) {
        #pragma unroll
        for (int ii = 0; ii < 2; ii++) {
            int i = i0 + ii;
            float* crow = g_cat + (size_t)i * DOUT;
            #pragma unroll
            for (int c = 0; c < 16; c++) crow[h * 16 + c] = ao[ii][c];
            float R[9];
            #pragma unroll
            for (int e = 0; e < 9; e++) R[e] = rot[i * 9 + e];
            float t0 = trans[i*3+0], t1 = trans[i*3+1], t2 = trans[i*3+2];
            #pragma unroll
            for (int p = 0; p < 8; p++) {
                float dx = ap[ii][p*3+0] - t0;
                float dy = ap[ii][p*3+1] - t1;
                float dz = ap[ii][p*3+2] - t2;
                float lx = R[0]*dx + R[3]*dy + R[6]*dz;
                float ly = R[1]*dx + R[4]*dy + R[7]*dz;
                float lz = R[2]*dx + R[5]*dy + R[8]*dz;
                crow[192 + (h*8+p)*3 + 0] = lx;
                crow[192 + (h*8+p)*3 + 1] = ly;
                crow[192 + (h*8+p)*3 + 2] = lz;
                crow[480 + h*8 + p] = sqrtf(lx*lx + ly*ly + lz*lz + 1e-8f);
            }
        }
    }
}

// ---------------- host ----------------
extern "C" void kernel_launch(void* const* d_in, const int* in_sizes, int n_in,
                              void* d_out, int out_size) {
    const float* s      = (const float*)d_in[0];
    const float* z      = (const float*)d_in[1];
    const float* rot    = (const float*)d_in[2];
    const float* trans  = (const float*)d_in[3];
    const float* mask   = (const float*)d_in[4];
    const float* w_q    = (const float*)d_in[5];
    const float* b_q    = (const float*)d_in[6];
    const float* w_kv   = (const float*)d_in[7];
    const float* b_kv   = (const float*)d_in[8];
    const float* w_qp   = (const float*)d_in[9];
    const float* b_qp   = (const float*)d_in[10];
    const float* w_kvp  = (const float*)d_in[11];
    const float* b_kvp  = (const float*)d_in[12];
    const float* w_b    = (const float*)d_in[13];
    const float* b_b    = (const float*)d_in[14];
    const float* hw     = (const float*)d_in[15];
    const float* w_out  = (const float*)d_in[16];
    const float* b_out  = (const float*)d_in[17];
    float* out = (float*)d_out;

    cudaFuncSetAttribute(bias_gemm,    cudaFuncAttributeMaxDynamicSharedMemorySize, SMA_BYTES);
    cudaFuncSetAttribute(attn_logits2, cudaFuncAttributeMaxDynamicSharedMemorySize, SMB_BYTES);
    cudaFuncSetAttribute(opair,        cudaFuncAttributeMaxDynamicSharedMemorySize, SMC_BYTES);

    copy_weights<<<(NPROJ * CSd + 255) / 256, 256>>>(w_q, b_q, w_kv, b_kv,
                                                     w_qp, b_qp, w_kvp, b_kvp);
    gemm_proj<<<dim3(NPROJ / 64, Nn / 64), 256>>>(s);
    prep_pts<<<Nn, 128>>>(rot, trans);
    bias_gemm<<<Nn, 256, SMA_BYTES>>>(z, w_b, b_b);
    attn_logits2<<<Nn / 2, 384, SMB_BYTES>>>(mask, hw);
    opair<<<dim3(2, Nn), 128, SMC_BYTES>>>(z);
    attn_out<<<Nn / 2, 384>>>(rot, trans);
    gemm_out_split<<<dim3(CSd / 64, Nn / 64, 3), 256>>>(w_out);
    gemm_out_combine<<<(Nn * CSd + 255) / 256, 256>>>(b_out, out);
}

// round 14
// speedup vs baseline: 4.0107x; 1.0107x over previous
#include <cuda_runtime.h>
#include <cstdint>
#include <cmath>

#define Nn    768
#define CSd   384
#define NPROJ 1152
#define DOUT  2112
#define INFV  100000.0f

__device__ float g_proj [Nn * NPROJ];
__device__ float g_wcat [NPROJ * CSd];
__device__ float g_bcat [NPROJ];
__device__ float g_kh  [12 * Nn * 16];
__device__ float g_vh  [12 * Nn * 16];
__device__ float g_kph [12 * Nn * 12];
__device__ float g_vph [12 * Nn * 24];
__device__ float g_qpts[Nn * 144];
__device__ float g_bias[(size_t)12 * Nn * Nn];
__device__ float g_a   [(size_t)12 * Nn * Nn];
__device__ float g_cat [Nn * DOUT];
__device__ float g_part[3 * Nn * CSd];

__device__ __forceinline__ void ffma2(unsigned long long& d,
                                      unsigned long long a,
                                      unsigned long long b) {
    asm("fma.rn.f32x2 %0, %1, %2, %0;" : "+l"(d) : "l"(a), "l"(b));
}
union F2U { unsigned long long u; float2 f; };

__device__ __forceinline__ uint32_t smaddr(const void* p) {
    return (uint32_t)__cvta_generic_to_shared(p);
}
__device__ __forceinline__ void cp16(uint32_t dst, const void* src) {
    asm volatile("cp.async.cg.shared.global [%0], [%1], 16;" :: "r"(dst), "l"(src));
}
__device__ __forceinline__ void cp_commit() {
    asm volatile("cp.async.commit_group;");
}
template<int N> __device__ __forceinline__ void cp_wait() {
    asm volatile("cp.async.wait_group %0;" :: "n"(N));
}

// ---------------- K0a: concat projection weights ----------------
__global__ void copy_weights(const float* __restrict__ wq,  const float* __restrict__ bq,
                             const float* __restrict__ wkv, const float* __restrict__ bkv,
                             const float* __restrict__ wqp, const float* __restrict__ bqp,
                             const float* __restrict__ wkvp,const float* __restrict__ bkvp) {
    int idx = blockIdx.x * 256 + threadIdx.x;
    if (idx < NPROJ * CSd) {
        int r = idx / CSd, k = idx - r * CSd;
        float v;
        if      (r < 192) v = wq  [ r        * CSd + k];
        else if (r < 576) v = wkv [(r - 192) * CSd + k];
        else if (r < 720) v = wqp [(r - 576) * CSd + k];
        else              v = wkvp[(r - 720) * CSd + k];
        g_wcat[idx] = v;
    }
    if (idx < NPROJ) {
        int r = idx;
        g_bcat[r] = (r < 192) ? bq[r] : (r < 576) ? bkv[r-192]
                  : (r < 720) ? bqp[r-576] : bkvp[r-720];
    }
}

// ---------------- projection GEMM ----------------
__global__ void gemm_proj(const float* __restrict__ A) {
    constexpr int KK = CSd;
    constexpr int NC = NPROJ;
    const float* B    = g_wcat;
    const float* bias = g_bcat;
    float*       C    = g_proj;

    __shared__ float As[64][17];
    __shared__ float Bs[64][17];
    int t  = threadIdx.x;
    int m0 = blockIdx.y * 64, n0 = blockIdx.x * 64;
    int lr = t >> 2, lc = (t & 3) * 4;
    int ty = (t >> 4) * 4, tx = (t & 15) * 4;
    float acc[4][4] = {};

    for (int k0 = 0; k0 < KK; k0 += 16) {
        __syncthreads();
        float4 a4 = *(const float4*)(A + (size_t)(m0 + lr) * KK + k0 + lc);
        float4 b4 = *(const float4*)(B + (size_t)(n0 + lr) * KK + k0 + lc);
        As[lr][lc] = a4.x; As[lr][lc+1] = a4.y; As[lr][lc+2] = a4.z; As[lr][lc+3] = a4.w;
        Bs[lr][lc] = b4.x; Bs[lr][lc+1] = b4.y; Bs[lr][lc+2] = b4.z; Bs[lr][lc+3] = b4.w;
        __syncthreads();
        #pragma unroll
        for (int kk = 0; kk < 16; kk++) {
            float av[4], bv[4];
            #pragma unroll
            for (int r = 0; r < 4; r++) av[r] = As[ty + r][kk];
            #pragma unroll
            for (int c = 0; c < 4; c++) bv[c] = Bs[tx + c][kk];
            #pragma unroll
            for (int r = 0; r < 4; r++)
                #pragma unroll
                for (int c = 0; c < 4; c++)
                    acc[r][c] = fmaf(av[r], bv[c], acc[r][c]);
        }
    }
    #pragma unroll
    for (int r = 0; r < 4; r++)
        #pragma unroll
        for (int c = 0; c < 4; c++)
            C[(size_t)(m0 + ty + r) * NC + n0 + tx + c] = acc[r][c] + bias[n0 + tx + c];
}

// ---------------- output GEMM, K split 3 ----------------
__global__ void gemm_out_split(const float* __restrict__ w_out) {
    constexpr int KCH = DOUT / 3;    // 704
    const float* A = g_cat;
    const float* B = w_out;
    int kc = blockIdx.z;
    float* C = g_part + (size_t)kc * Nn * CSd;

    __shared__ float As[64][17];
    __shared__ float Bs[64][17];
    int t  = threadIdx.x;
    int m0 = blockIdx.y * 64, n0 = blockIdx.x * 64;
    int lr = t >> 2, lc = (t & 3) * 4;
    int ty = (t >> 4) * 4, tx = (t & 15) * 4;
    float acc[4][4] = {};

    for (int k0 = kc * KCH; k0 < (kc + 1) * KCH; k0 += 16) {
        __syncthreads();
        float4 a4 = *(const float4*)(A + (size_t)(m0 + lr) * DOUT + k0 + lc);
        float4 b4 = *(const float4*)(B + (size_t)(n0 + lr) * DOUT + k0 + lc);
        As[lr][lc] = a4.x; As[lr][lc+1] = a4.y; As[lr][lc+2] = a4.z; As[lr][lc+3] = a4.w;
        Bs[lr][lc] = b4.x; Bs[lr][lc+1] = b4.y; Bs[lr][lc+2] = b4.z; Bs[lr][lc+3] = b4.w;
        __syncthreads();
        #pragma unroll
        for (int kk = 0; kk < 16; kk++) {
            float av[4], bv[4];
            #pragma unroll
            for (int r = 0; r < 4; r++) av[r] = As[ty + r][kk];
            #pragma unroll
            for (int c = 0; c < 4; c++) bv[c] = Bs[tx + c][kk];
            #pragma unroll
            for (int r = 0; r < 4; r++)
                #pragma unroll
                for (int c = 0; c < 4; c++)
                    acc[r][c] = fmaf(av[r], bv[c], acc[r][c]);
        }
    }
    #pragma unroll
    for (int r = 0; r < 4; r++)
        #pragma unroll
        for (int c = 0; c < 4; c++)
            C[(size_t)(m0 + ty + r) * CSd + n0 + tx + c] = acc[r][c];
}

__global__ void gemm_out_combine(const float* __restrict__ b_out, float* __restrict__ out) {
    int idx = blockIdx.x * 256 + threadIdx.x;
    if (idx < Nn * CSd) {
        int c = idx % CSd;
        out[idx] = g_part[idx] + g_part[idx + Nn * CSd] + g_part[idx + 2 * Nn * CSd]
                 + b_out[c];
    }
}

// ---------------- K0b: rotate points, repack k/v into [h][j][*] ----------------
__global__ void prep_pts(const float* __restrict__ rot, const float* __restrict__ trans) {
    int n = blockIdx.x;
    const float* pr = g_proj + (size_t)n * NPROJ;
    float R[9];
    #pragma unroll
    for (int e = 0; e < 9; e++) R[e] = rot[n * 9 + e];
    float tr[3] = {trans[n*3+0], trans[n*3+1], trans[n*3+2]};

    for (int t = threadIdx.x; t < 960; t += blockDim.x) {
        if (t < 384) {
            int h = t >> 5, c = t & 31;
            float v = pr[192 + h * 32 + c];
            if (c < 16) g_kh[((size_t)h * Nn + n) * 16 + c]        = v;
            else        g_vh[((size_t)h * Nn + n) * 16 + (c - 16)] = v;
        } else if (t < 528) {
            int e = t - 384;
            int g = e / 3, ax = e - g * 3;
            const float* src = pr + 576 + g * 3;
            g_qpts[n * 144 + e] =
                R[ax*3+0]*src[0] + R[ax*3+1]*src[1] + R[ax*3+2]*src[2] + tr[ax];
        } else {
            int e2 = t - 528;
            int g = e2 / 3, ax = e2 - g * 3;
            const float* src = pr + 720 + g * 3;
            float val = R[ax*3+0]*src[0] + R[ax*3+1]*src[1] + R[ax*3+2]*src[2] + tr[ax];
            int h = g / 12, pp = g - h * 12;
            if (pp < 4) g_kph[((size_t)h * Nn + n) * 12 + pp * 3 + ax]       = val;
            else        g_vph[((size_t)h * Nn + n) * 24 + (pp - 4) * 3 + ax] = val;
        }
    }
}

// ---------------- KA: bias GEMM v3 — 2 rows/thread, cp.async pipeline -----------
// threads: cg = t>>5 (c4 in [cg*4,cg*4+4)), jl = t&31 (rows jl, jl+32)
// smem floats: zb[2][8192] | swb 1536 | sbb 16 | part 6144  = 24080
#define SMA_BYTES (24080 * 4)
__global__ __launch_bounds__(256) void bias_gemm(const float* __restrict__ z,
                                                 const float* __restrict__ w_b,
                                                 const float* __restrict__ b_b) {
    extern __shared__ float sm[];
    float* swb  = sm + 16384;
    float* sbb  = sm + 17920;
    float* part = sm + 17936;   // [8 cg][12 h][64 j]

    const int i = blockIdx.x;
    const int t = threadIdx.x;
    const int cg = t >> 5, jl = t & 31;

    for (int idx = t; idx < 384; idx += 256)
        ((float4*)swb)[idx] = ((const float4*)w_b)[idx];
    if (t < 12) sbb[t] = b_b[t];

    const float4* zbase = (const float4*)z + (size_t)i * Nn * 32;

    #pragma unroll
    for (int p = 0; p < 2; p++) {
        float* buf = sm + p * 8192;
        const float4* src = zbase + (size_t)p * 64 * 32;
        #pragma unroll
        for (int k = 0; k < 8; k++) {
            int idx = t + k * 256;
            int jj = idx >> 5, c4 = idx & 31;
            cp16(smaddr(buf + (size_t)(jj * 32 + (c4 ^ (jj & 31))) * 4),
                 src + (size_t)jj * 32 + c4);
        }
        cp_commit();
    }

    for (int tt = 0; tt < 12; tt++) {
        if (tt < 11) cp_wait<1>(); else cp_wait<0>();
        __syncthreads();

        const float* zr = sm + (tt & 1) * 8192;
        // rows jl and jl+32 — both have low5 = jl, so swizzle term is jl
        ulonglong2 zz[2][4];
        #pragma unroll
        for (int e = 0; e < 2; e++) {
            const float* rp = zr + (jl + 32 * e) * 128;
            #pragma unroll
            for (int cc = 0; cc < 4; cc++) {
                int c4 = cg * 4 + cc;
                zz[e][cc] = *(const ulonglong2*)(rp + ((c4 ^ jl) << 2));
            }
        }
        unsigned long long acc[12][2] = {};
        #pragma unroll
        for (int h = 0; h < 12; h++) {
            #pragma unroll
            for (int cc = 0; cc < 4; cc++) {
                int c4 = cg * 4 + cc;
                ulonglong2 ww = *(const ulonglong2*)(swb + h * 128 + (c4 << 2));
                ffma2(acc[h][0], zz[0][cc].x, ww.x);
                ffma2(acc[h][0], zz[0][cc].y, ww.y);
                ffma2(acc[h][1], zz[1][cc].x, ww.x);
                ffma2(acc[h][1], zz[1][cc].y, ww.y);
            }
        }
        #pragma unroll
        for (int h = 0; h < 12; h++) {
            F2U u0; u0.u = acc[h][0];
            F2U u1; u1.u = acc[h][1];
            part[(cg * 12 + h) * 64 + jl]      = u0.f.x + u0.f.y;
            part[(cg * 12 + h) * 64 + jl + 32] = u1.f.x + u1.f.y;
        }
        __syncthreads();   // part done; zb[tt&1] fully consumed

        if (tt + 2 < 12) {
            float* buf = sm + (tt & 1) * 8192;
            const float4* src = zbase + (size_t)(tt + 2) * 64 * 32;
            #pragma unroll
            for (int k = 0; k < 8; k++) {
                int idx = t + k * 256;
                int jj = idx >> 5, c4 = idx & 31;
                cp16(smaddr(buf + (size_t)(jj * 32 + (c4 ^ (jj & 31))) * 4),
                     src + (size_t)jj * 32 + c4);
            }
            cp_commit();
        }

        #pragma unroll
        for (int r = t; r < 768; r += 256) {
            int h = r >> 6, j = r & 63;
            float s2 = 0.f;
            #pragma unroll
            for (int c = 0; c < 8; c++) s2 += part[(c * 12 + h) * 64 + j];
            g_bias[((size_t)h * Nn + i) * Nn + tt * 64 + j] =
                0.5773502691896258f * (s2 + sbb[h]);
        }
    }
}

// ---------------- KB: fused logits + softmax; warp = h, 2 i's per CTA ----------
#define SMB_BYTES (12 * 2 * 768 * 4)
__global__ __launch_bounds__(384) void attn_logits2(const float* __restrict__ mask,
                                                    const float* __restrict__ hwraw) {
    extern __shared__ float srows[];
    int i0 = blockIdx.x * 2;
    int h = threadIdx.x >> 5, lane = threadIdx.x & 31;
    float* row0 = srows + (h * 2 + 0) * 768;
    float* row1 = srows + (h * 2 + 1) * 768;

    float q[2][16], qp[2][12];
    #pragma unroll
    for (int ii = 0; ii < 2; ii++) {
        const float4* qs = (const float4*)(g_proj + (size_t)(i0+ii) * NPROJ + h * 16);
        #pragma unroll
        for (int c = 0; c < 4; c++) {
            float4 v = qs[c];
            q[ii][c*4+0] = v.x; q[ii][c*4+1] = v.y; q[ii][c*4+2] = v.z; q[ii][c*4+3] = v.w;
        }
        const float4* ps = (const float4*)(g_qpts + (size_t)(i0+ii) * 144 + h * 12);
        #pragma unroll
        for (int c = 0; c < 3; c++) {
            float4 v = ps[c];
            qp[ii][c*4+0] = v.x; qp[ii][c*4+1] = v.y; qp[ii][c*4+2] = v.z; qp[ii][c*4+3] = v.w;
        }
    }
    float x = hwraw[h];
    float hwv = ((x > 20.f) ? x : log1pf(expf(x))) * 0.13608276348795434f;
    float mi0 = mask[i0], mi1 = mask[i0 + 1];
    const float s1 = 0.14433756729740643f;
    float mx0 = -3.4e38f, mx1 = -3.4e38f;

    for (int j0 = 0; j0 < Nn; j0 += 32) {
        int j = j0 + lane;
        float mj = mask[j];
        const float4* kb = (const float4*)(g_kh + ((size_t)h * Nn + j) * 16);
        float4 k0 = kb[0], k1 = kb[1], k2 = kb[2], k3 = kb[3];
        const float4* pb = (const float4*)(g_kph + ((size_t)h * Nn + j) * 12);
        float4 p0 = pb[0], p1 = pb[1], p2 = pb[2];

        #pragma unroll
        for (int ii = 0; ii < 2; ii++) {
            float qk = 0.f;
            qk = fmaf(q[ii][0],  k0.x, qk); qk = fmaf(q[ii][1],  k0.y, qk);
            qk = fmaf(q[ii][2],  k0.z, qk); qk = fmaf(q[ii][3],  k0.w, qk);
            qk = fmaf(q[ii][4],  k1.x, qk); qk = fmaf(q[ii][5],  k1.y, qk);
            qk = fmaf(q[ii][6],  k1.z, qk); qk = fmaf(q[ii][7],  k1.w, qk);
            qk = fmaf(q[ii][8],  k2.x, qk); qk = fmaf(q[ii][9],  k2.y, qk);
            qk = fmaf(q[ii][10], k2.z, qk); qk = fmaf(q[ii][11], k2.w, qk);
            qk = fmaf(q[ii][12], k3.x, qk); qk = fmaf(q[ii][13], k3.y, qk);
            qk = fmaf(q[ii][14], k3.z, qk); qk = fmaf(q[ii][15], k3.w, qk);

            float d2 = 0.f, d;
            d = qp[ii][0]  - p0.x; d2 = fmaf(d, d, d2);
            d = qp[ii][1]  - p0.y; d2 = fmaf(d, d, d2);
            d = qp[ii][2]  - p0.z; d2 = fmaf(d, d, d2);
            d = qp[ii][3]  - p0.w; d2 = fmaf(d, d, d2);
            d = qp[ii][4]  - p1.x; d2 = fmaf(d, d, d2);
            d = qp[ii][5]  - p1.y; d2 = fmaf(d, d, d2);
            d = qp[ii][6]  - p1.z; d2 = fmaf(d, d, d2);
            d = qp[ii][7]  - p1.w; d2 = fmaf(d, d, d2);
            d = qp[ii][8]  - p2.x; d2 = fmaf(d, d, d2);
            d = qp[ii][9]  - p2.y; d2 = fmaf(d, d, d2);
            d = qp[ii][10] - p2.z; d2 = fmaf(d, d, d2);
            d = qp[ii][11] - p2.w; d2 = fmaf(d, d, d2);

            float bias = g_bias[((size_t)h * Nn + i0 + ii) * Nn + j];
            float mi = ii ? mi1 : mi0;
            float lg = qk * s1 + bias - 0.5f * hwv * d2 + INFV * (mi * mj - 1.f);
            if (ii == 0) { row0[j] = lg; mx0 = fmaxf(mx0, lg); }
            else         { row1[j] = lg; mx1 = fmaxf(mx1, lg); }
        }
    }

    #pragma unroll
    for (int off = 16; off; off >>= 1) {
        mx0 = fmaxf(mx0, __shfl_xor_sync(0xffffffffu, mx0, off));
        mx1 = fmaxf(mx1, __shfl_xor_sync(0xffffffffu, mx1, off));
    }
    float s0 = 0.f, sum1 = 0.f;
    for (int jj = lane; jj < Nn; jj += 32) {
        float e0 = __expf(row0[jj] - mx0); row0[jj] = e0; s0   += e0;
        float e1 = __expf(row1[jj] - mx1); row1[jj] = e1; sum1 += e1;
    }
    #pragma unroll
    for (int off = 16; off; off >>= 1) {
        s0   += __shfl_xor_sync(0xffffffffu, s0,   off);
        sum1 += __shfl_xor_sync(0xffffffffu, sum1, off);
    }
    float inv0 = 1.0f / s0, inv1 = 1.0f / sum1;
    float* a0 = g_a + ((size_t)h * Nn + i0) * Nn;
    float* a1 = a0 + Nn;
    for (int jj = lane; jj < Nn; jj += 32) {
        a0[jj] = row0[jj] * inv0;
        a1[jj] = row1[jj] * inv1;
    }
}

// ---------------- KC: o_pair v2 — CTA=i, warp=4 j-rows, all 12 heads ------------
// smem floats: zb[2][4096] | sab[2][384] | pred[8][1536]  = 21248
#define SMC_BYTES (21248 * 4)
__global__ __launch_bounds__(256) void opair(const float* __restrict__ z) {
    extern __shared__ float smc[];
    float* zb   = smc;           // [2][32 j][128 ch]
    float* sab  = smc + 8192;    // [2][12 h][32 j]
    float* pred = smc + 8960;    // [8 w][12 h][128 ch]
    const int i = blockIdx.x;
    const int t = threadIdx.x, w = t >> 5, lane = t & 31;

    unsigned long long acc[12][2] = {};

    #pragma unroll
    for (int p = 0; p < 2; p++) {
        float* zdst = zb + p * 4096;
        float* adst = sab + p * 384;
        const float4* zsrc = (const float4*)z + ((size_t)i * Nn + p * 32) * 32;
        #pragma unroll
        for (int k = 0; k < 4; k++) {
            int idx = t + k * 256;
            cp16(smaddr(zdst + (size_t)idx * 4), zsrc + idx);
        }
        if (t < 96) {
            int hh = t >> 3, c = t & 7;
            cp16(smaddr(adst + (size_t)t * 4),
                 (const float4*)(g_a + ((size_t)hh * Nn + i) * Nn + p * 32) + c);
        }
        cp_commit();
    }

    for (int tt = 0; tt < 24; tt++) {
        if (tt < 23) cp_wait<1>(); else cp_wait<0>();
        __syncthreads();

        const float* sz = zb + (tt & 1) * 4096;
        const float* sa = sab + (tt & 1) * 384;
        const int jw = w * 4;

        float4 av[12];
        #pragma unroll
        for (int h = 0; h < 12; h++)
            av[h] = *(const float4*)(sa + h * 32 + jw);
        ulonglong2 zz[4];
        #pragma unroll
        for (int jj = 0; jj < 4; jj++)
            zz[jj] = *(const ulonglong2*)(sz + (jw + jj) * 128 + lane * 4);

        #pragma unroll
        for (int h = 0; h < 12; h++) {
            float a4[4] = {av[h].x, av[h].y, av[h].z, av[h].w};
            #pragma unroll
            for (int jj = 0; jj < 4; jj++) {
                F2U u; u.f.x = a4[jj]; u.f.y = a4[jj];
                ffma2(acc[h][0], u.u, zz[jj].x);
                ffma2(acc[h][1], u.u, zz[jj].y);
            }
        }
        __syncthreads();

        if (tt + 2 < 24) {
            float* zdst = zb + (tt & 1) * 4096;
            float* adst = sab + (tt & 1) * 384;
            const float4* zsrc = (const float4*)z + ((size_t)i * Nn + (tt + 2) * 32) * 32;
            #pragma unroll
            for (int k = 0; k < 4; k++) {
                int idx = t + k * 256;
                cp16(smaddr(zdst + (size_t)idx * 4), zsrc + idx);
            }
            if (t < 96) {
                int hh = t >> 3, c = t & 7;
                cp16(smaddr(adst + (size_t)t * 4),
                     (const float4*)(g_a + ((size_t)hh * Nn + i) * Nn + (tt + 2) * 32) + c);
            }
            cp_commit();
        }
    }

    // per-warp partials -> smem -> 8-way reduce
    #pragma unroll
    for (int h = 0; h < 12; h++) {
        F2U lo, hi; lo.u = acc[h][0]; hi.u = acc[h][1];
        float4 v = {lo.f.x, lo.f.y, hi.f.x, hi.f.y};
        *(float4*)(pred + (w * 12 + h) * 128 + lane * 4) = v;
    }
    __syncthreads();
    float* crow = g_cat + (size_t)i * DOUT + 576;
    for (int r = t; r < 1536; r += 256) {
        float s2 = 0.f;
        #pragma unroll
        for (int wp = 0; wp < 8; wp++) s2 += pred[wp * 1536 + r];
        crow[r] = s2;
    }
}

// ---------------- KD: o + o_pt + inverse frame + norms; 2 i's per CTA ----------
__global__ __launch_bounds__(384) void attn_out(const float* __restrict__ rot,
                                                const float* __restrict__ trans) {
    int i0 = blockIdx.x * 2;
    int h = threadIdx.x >> 5, lane = threadIdx.x & 31;

    float ao[2][16] = {};
    float ap[2][24] = {};

    for (int j0 = 0; j0 < Nn; j0 += 32) {
        int j = j0 + lane;
        const float4* vb = (const float4*)(g_vh + ((size_t)h * Nn + j) * 16);
        float4 v0 = vb[0], v1 = vb[1], v2 = vb[2], v3 = vb[3];
        const float4* pb = (const float4*)(g_vph + ((size_t)h * Nn + j) * 24);
        float4 p0 = pb[0], p1 = pb[1], p2 = pb[2], p3 = pb[3], p4 = pb[4], p5 = pb[5];

        #pragma unroll
        for (int ii = 0; ii < 2; ii++) {
            float a = g_a[((size_t)h * Nn + i0 + ii) * Nn + j];
            ao[ii][0]  = fmaf(a, v0.x, ao[ii][0]);  ao[ii][1]  = fmaf(a, v0.y, ao[ii][1]);
            ao[ii][2]  = fmaf(a, v0.z, ao[ii][2]);  ao[ii][3]  = fmaf(a, v0.w, ao[ii][3]);
            ao[ii][4]  = fmaf(a, v1.x, ao[ii][4]);  ao[ii][5]  = fmaf(a, v1.y, ao[ii][5]);
            ao[ii][6]  = fmaf(a, v1.z, ao[ii][6]);  ao[ii][7]  = fmaf(a, v1.w, ao[ii][7]);
            ao[ii][8]  = fmaf(a, v2.x, ao[ii][8]);  ao[ii][9]  = fmaf(a, v2.y, ao[ii][9]);
            ao[ii][10] = fmaf(a, v2.z, ao[ii][10]); ao[ii][11] = fmaf(a, v2.w, ao[ii][11]);
            ao[ii][12] = fmaf(a, v3.x, ao[ii][12]); ao[ii][13] = fmaf(a, v3.y, ao[ii][13]);
            ao[ii][14] = fmaf(a, v3.z, ao[ii][14]); ao[ii][15] = fmaf(a, v3.w, ao[ii][15]);

            ap[ii][0]  = fmaf(a, p0.x, ap[ii][0]);  ap[ii][1]  = fmaf(a, p0.y, ap[ii][1]);
            ap[ii][2]  = fmaf(a, p0.z, ap[ii][2]);  ap[ii][3]  = fmaf(a, p0.w, ap[ii][3]);
            ap[ii][4]  = fmaf(a, p1.x, ap[ii][4]);  ap[ii][5]  = fmaf(a, p1.y, ap[ii][5]);
            ap[ii][6]  = fmaf(a, p1.z, ap[ii][6]);  ap[ii][7]  = fmaf(a, p1.w, ap[ii][7]);
            ap[ii][8]  = fmaf(a, p2.x, ap[ii][8]);  ap[ii][9]  = fmaf(a, p2.y, ap[ii][9]);
            ap[ii][10] = fmaf(a, p2.z, ap[ii][10]); ap[ii][11] = fmaf(a, p2.w, ap[ii][11]);
            ap[ii][12] = fmaf(a, p3.x, ap[ii][12]); ap[ii][13] = fmaf(a, p3.y, ap[ii][13]);
            ap[ii][14] = fmaf(a, p3.z, ap[ii][14]); ap[ii][15] = fmaf(a, p3.w, ap[ii][15]);
            ap[ii][16] = fmaf(a, p4.x, ap[ii][16]); ap[ii][17] = fmaf(a, p4.y, ap[ii][17]);
            ap[ii][18] = fmaf(a, p4.z, ap[ii][18]); ap[ii][19] = fmaf(a, p4.w, ap[ii][19]);
            ap[ii][20] = fmaf(a, p5.x, ap[ii][20]); ap[ii][21] = fmaf(a, p5.y, ap[ii][21]);
            ap[ii][22] = fmaf(a, p5.z, ap[ii][22]); ap[ii][23] = fmaf(a, p5.w, ap[ii][23]);
        }
    }

    #pragma unroll
    for (int off = 16; off; off >>= 1) {
        #pragma unroll
        for (int ii = 0; ii < 2; ii++) {
            #pragma unroll
            for (int c = 0; c < 16; c++) ao[ii][c] += __shfl_xor_sync(0xffffffffu, ao[ii][c], off);
            #pragma unroll
            for (int e = 0; e < 24; e++) ap[ii][e] += __shfl_xor_sync(0xffffffffu, ap[ii][e], off);
        }
    }

    if (lane == 0) {
        #pragma unroll
        for (int ii = 0; ii < 2; ii++) {
            int i = i0 + ii;
            float* crow = g_cat + (size_t)i * DOUT;
            #pragma unroll
            for (int c = 0; c < 16; c++) crow[h * 16 + c] = ao[ii][c];
            float R[9];
            #pragma unroll
            for (int e = 0; e < 9; e++) R[e] = rot[i * 9 + e];
            float t0 = trans[i*3+0], t1 = trans[i*3+1], t2 = trans[i*3+2];
            #pragma unroll
            for (int p = 0; p < 8; p++) {
                float dx = ap[ii][p*3+0] - t0;
                float dy = ap[ii][p*3+1] - t1;
                float dz = ap[ii][p*3+2] - t2;
                float lx = R[0]*dx + R[3]*dy + R[6]*dz;
                float ly = R[1]*dx + R[4]*dy + R[7]*dz;
                float lz = R[2]*dx + R[5]*dy + R[8]*dz;
                crow[192 + (h*8+p)*3 + 0] = lx;
                crow[192 + (h*8+p)*3 + 1] = ly;
                crow[192 + (h*8+p)*3 + 2] = lz;
                crow[480 + h*8 + p] = sqrtf(lx*lx + ly*ly + lz*lz + 1e-8f);
            }
        }
    }
}

// ---------------- host ----------------
extern "C" void kernel_launch(void* const* d_in, const int* in_sizes, int n_in,
                              void* d_out, int out_size) {
    const float* s      = (const float*)d_in[0];
    const float* z      = (const float*)d_in[1];
    const float* rot    = (const float*)d_in[2];
    const float* trans  = (const float*)d_in[3];
    const float* mask   = (const float*)d_in[4];
    const float* w_q    = (const float*)d_in[5];
    const float* b_q    = (const float*)d_in[6];
    const float* w_kv   = (const float*)d_in[7];
    const float* b_kv   = (const float*)d_in[8];
    const float* w_qp   = (const float*)d_in[9];
    const float* b_qp   = (const float*)d_in[10];
    const float* w_kvp  = (const float*)d_in[11];
    const float* b_kvp  = (const float*)d_in[12];
    const float* w_b    = (const float*)d_in[13];
    const float* b_b    = (const float*)d_in[14];
    const float* hw     = (const float*)d_in[15];
    const float* w_out  = (const float*)d_in[16];
    const float* b_out  = (const float*)d_in[17];
    float* out = (float*)d_out;

    cudaFuncSetAttribute(bias_gemm,    cudaFuncAttributeMaxDynamicSharedMemorySize, SMA_BYTES);
    cudaFuncSetAttribute(attn_logits2, cudaFuncAttributeMaxDynamicSharedMemorySize, SMB_BYTES);
    cudaFuncSetAttribute(opair,        cudaFuncAttributeMaxDynamicSharedMemorySize, SMC_BYTES);

    copy_weights<<<(NPROJ * CSd + 255) / 256, 256>>>(w_q, b_q, w_kv, b_kv,
                                                     w_qp, b_qp, w_kvp, b_kvp);
    gemm_proj<<<dim3(NPROJ / 64, Nn / 64), 256>>>(s);
    prep_pts<<<Nn, 128>>>(rot, trans);
    bias_gemm<<<Nn, 256, SMA_BYTES>>>(z, w_b, b_b);
    attn_logits2<<<Nn / 2, 384, SMB_BYTES>>>(mask, hw);
    opair<<<Nn, 256, SMC_BYTES>>>(z);
    attn_out<<<Nn / 2, 384>>>(rot, trans);
    gemm_out_split<<<dim3(CSd / 64, Nn / 64, 3), 256>>>(w_out);
    gemm_out_combine<<<(Nn * CSd + 255) / 256, 256>>>(b_out, out);
}